// round 8
// baseline (speedup 1.0000x reference)
#include <cuda_runtime.h>

#define NN 10000
#define NE 160000

#define SILU_C_F   1.6765867f
#define INV_S8     0.35355339059327373f
#define INV_S32    0.17677669529663687f
#define INV_S96    0.10206207261596575f
#define INV_S128   0.08838834764831845f
#define INV_S3     0.57735026918962576f
#define S3_DIV_S5  0.77459666924148338f   // sqrt(3/5)
#define IS2        0.70710678118654752f   // 1/sqrt(2)
#define IS6        0.40824829046386302f   // 1/sqrt(6)
#define C_S        0.38268343236508977f   // sin(pi/8)
#define C_X        0.92387953251128676f   // cos(pi/8)

// scratch
__device__ float g_y[NN * 160];
__device__ float g_s[NN * 160];     // self-connection, C_S pre-folded
// sort scratch
__device__ int g_count[NN];
__device__ int g_fill[NN];
__device__ int g_offset[NN + 1];
__device__ int g_perm[NE];
// transposed weights (norm constants folded)
__device__ float g_w0T[64 * 96];    // lin2_w0^T * C_X/sqrt(96)
__device__ float g_w1T[32 * 128];   // lin2_w1^T * C_X/sqrt(128)
__device__ float g_w2T[32 * 96];    // lin2_w2^T * 1/sqrt(96)
__device__ float g_l1w0T[64 * 64];
__device__ float g_scw0T[64 * 64];
__device__ float g_l1w1T[32 * 32];
__device__ float g_scw1T[32 * 32];

// ---------------- zero counters ----------------
__global__ void k_zero() {
    int i = blockIdx.x * blockDim.x + threadIdx.x;
    if (i < NN) { g_count[i] = 0; g_fill[i] = 0; }
}

// ---------------- histogram / scan / permutation ----------------
__global__ void k_hist(const int* __restrict__ edge_dst) {
    int i = blockIdx.x * blockDim.x + threadIdx.x;
    if (i < NE) atomicAdd(&g_count[edge_dst[i]], 1);
}
__global__ __launch_bounds__(512) void k_scan() {
    __shared__ int part[512];
    int t = threadIdx.x;
    int base = t * 20;
    int s = 0;
    #pragma unroll
    for (int i = 0; i < 20; i++) { int idx = base + i; if (idx < NN) s += g_count[idx]; }
    part[t] = s;
    __syncthreads();
    for (int d = 1; d < 512; d <<= 1) {
        int v = (t >= d) ? part[t - d] : 0;
        __syncthreads();
        part[t] += v;
        __syncthreads();
    }
    int run = (t > 0) ? part[t - 1] : 0;
    for (int i = 0; i < 20; i++) {
        int idx = base + i;
        if (idx < NN) { g_offset[idx] = run; run += g_count[idx]; }
    }
    if (t == 511) g_offset[NN] = run;
}
__global__ void k_fill(const int* __restrict__ edge_dst) {
    int e = blockIdx.x * blockDim.x + threadIdx.x;
    if (e < NE) {
        int d = edge_dst[e];
        int p = atomicAdd(&g_fill[d], 1);
        g_perm[g_offset[d] + p] = e;
    }
}

// ---------------- transpose weights (fold output constants) ----------------
__global__ void k_tw(const float* __restrict__ lin2_w0, const float* __restrict__ lin2_w1,
                     const float* __restrict__ lin2_w2, const float* __restrict__ lin1_w0,
                     const float* __restrict__ lin1_w1, const float* __restrict__ sc_w0,
                     const float* __restrict__ sc_w1) {
    int idx = blockIdx.x * blockDim.x + threadIdx.x;
    if (idx < 6144) { int c = idx / 96, p = idx % 96;
        g_w0T[idx] = lin2_w0[p * 64 + c] * (C_X * INV_S96); return; }
    idx -= 6144;
    if (idx < 4096) { int c = idx / 128, p = idx % 128;
        g_w1T[idx] = lin2_w1[p * 32 + c] * (C_X * INV_S128); return; }
    idx -= 4096;
    if (idx < 3072) { int c = idx / 96, p = idx % 96;
        g_w2T[idx] = lin2_w2[p * 32 + c] * INV_S96; return; }
    idx -= 3072;
    if (idx < 4096) { int c = idx / 64, u = idx % 64; g_l1w0T[idx] = lin1_w0[u * 64 + c]; return; }
    idx -= 4096;
    if (idx < 4096) { int c = idx / 64, u = idx % 64; g_scw0T[idx] = sc_w0[u * 64 + c]; return; }
    idx -= 4096;
    if (idx < 1024) { int c = idx / 32, u = idx % 32; g_l1w1T[idx] = lin1_w1[u * 32 + c]; return; }
    idx -= 1024;
    if (idx < 1024) { int c = idx / 32, u = idx % 32; g_scw1T[idx] = sc_w1[u * 32 + c]; return; }
}

// ---------------- node pre-linear ----------------
__global__ __launch_bounds__(160) void k_node(
    const float* __restrict__ node_input, const float* __restrict__ node_attr)
{
    __shared__ float xs[160];
    __shared__ float xsT[96];
    int n = blockIdx.x, t = threadIdx.x;
    xs[t] = node_input[n * 160 + t];
    __syncthreads();
    if (t < 96) { int i = t >> 5, u = t & 31; xsT[t] = xs[64 + u * 3 + i]; }
    __syncthreads();
    float a = node_attr[n];
    if (t < 64) {
        float ay = 0.f, as = 0.f;
        #pragma unroll
        for (int u = 0; u < 64; u += 4) {
            float4 xv = *reinterpret_cast<const float4*>(xs + u);
            float4 wy = *reinterpret_cast<const float4*>(g_l1w0T + t * 64 + u);
            float4 ws = *reinterpret_cast<const float4*>(g_scw0T + t * 64 + u);
            ay = fmaf(xv.x, wy.x, fmaf(xv.y, wy.y, fmaf(xv.z, wy.z, fmaf(xv.w, wy.w, ay))));
            as = fmaf(xv.x, ws.x, fmaf(xv.y, ws.y, fmaf(xv.z, ws.z, fmaf(xv.w, ws.w, as))));
        }
        g_y[n * 160 + t] = ay * a * 0.125f;
        g_s[n * 160 + t] = as * a * (0.125f * C_S);
    } else {
        int j = t - 64, v = j / 3, i = j - 3 * v;
        float ay = 0.f, as = 0.f;
        #pragma unroll
        for (int u = 0; u < 32; u += 4) {
            float4 xv = *reinterpret_cast<const float4*>(xsT + i * 32 + u);
            float4 wy = *reinterpret_cast<const float4*>(g_l1w1T + v * 32 + u);
            float4 ws = *reinterpret_cast<const float4*>(g_scw1T + v * 32 + u);
            ay = fmaf(xv.x, wy.x, fmaf(xv.y, wy.y, fmaf(xv.z, wy.z, fmaf(xv.w, wy.w, ay))));
            as = fmaf(xv.x, ws.x, fmaf(xv.y, ws.y, fmaf(xv.z, ws.z, fmaf(xv.w, ws.w, as))));
        }
        g_y[n * 160 + t] = ay * a * INV_S32;
        g_s[n * 160 + t] = as * a * (INV_S32 * C_S);
    }
}

// ---------------- mega kernel: gather per dst node, zero atomics ----------------
// thread t owns fc_w1 column t (in registers). Output-column ownership:
//   t in [0,64)    : k0  -> m[t]                      (1 acc)
//   t in [64,128)  : k2  -> m1T[k*128 + (t-64)]       (3 accs)
//   t in [128,192) : k5  -> m2T[k*96 + (t-128)]       (5 accs)
//   t in [192,224) : k3  -> m1T[k*128 + 64 + v]       (3 accs)
//   t in [224,256) : k1  -> m[64 + v]                 (1 acc)
//   t in [256,288) : k6  -> m2T[k*96 + 64 + v]        (5 accs)
//   t in [288,320) : k4  -> m1T[k*128 + 96 + v]       (3 accs)
__global__ __launch_bounds__(320, 2) void k_mega(
    const float* __restrict__ edge_attr, const float* __restrict__ ele,
    const int* __restrict__ edge_src, const float* __restrict__ node_attr,
    const float* __restrict__ fc_w1, const float* __restrict__ fc_w0,
    float* __restrict__ out)
{
    __shared__ float hb[2][64];
    __shared__ float s_w0[512];
    __shared__ float m[96];
    __shared__ float m1T[3 * 128];
    __shared__ float m2T[5 * 96];

    int n = blockIdx.x, t = threadIdx.x;
    for (int i = t; i < 512; i += 320) s_w0[i] = fc_w0[i];

    float wcol[64];
    #pragma unroll
    for (int k = 0; k < 64; k++) wcol[k] = __ldg(&fc_w1[k * 320 + t]);
    float acc0 = 0.f, acc1 = 0.f, acc2 = 0.f, acc3 = 0.f, acc4 = 0.f;

    int off = g_offset[n];
    int deg = g_offset[n + 1] - off;
    __syncthreads();   // s_w0 ready

    if (deg > 0) {
        // prologue: edge 0
        int ed = __ldg(&g_perm[off]);
        int src = __ldg(&edge_src[ed]);
        float yv0 = 0.f, yv1 = 0.f, yv2 = 0.f;
        if (t < 192) {
            yv0 = __ldg(&g_y[src * 160 + (t & 63)]);
        } else {
            const float* yp = &g_y[src * 160 + 64 + 3 * ((t - 192) & 31)];
            yv0 = __ldg(yp); yv1 = __ldg(yp + 1); yv2 = __ldg(yp + 2);
        }
        if (t < 64) {
            float z = 0.f;
            #pragma unroll
            for (int k = 0; k < 8; k++) z = fmaf(__ldg(&ele[ed * 8 + k]), s_w0[k * 64 + t], z);
            z *= INV_S8;
            float sg = __fdividef(1.f, 1.f + __expf(-z));
            hb[0][t] = z * sg * (SILU_C_F * 0.03125f);
        }
        __syncthreads();

        int par = 0;
        for (int i = 0; i < deg; i++) {
            bool more = (i + 1 < deg);
            int ed_n = 0, src_n = 0;
            float el_n[8];
            if (more) {
                ed_n = __ldg(&g_perm[off + i + 1]);
                src_n = __ldg(&edge_src[ed_n]);
                if (t < 64) {
                    #pragma unroll
                    for (int k = 0; k < 8; k++) el_n[k] = __ldg(&ele[ed_n * 8 + k]);
                }
            }

            // w[t] = h . fc_w1[:,t]   (broadcast LDS of h, register weights)
            float d0 = 0.f, d1 = 0.f, d2 = 0.f, d3 = 0.f;
            #pragma unroll
            for (int k = 0; k < 64; k += 16) {
                float4 h0 = *reinterpret_cast<const float4*>(&hb[par][k]);
                float4 h1 = *reinterpret_cast<const float4*>(&hb[par][k + 4]);
                float4 h2 = *reinterpret_cast<const float4*>(&hb[par][k + 8]);
                float4 h3 = *reinterpret_cast<const float4*>(&hb[par][k + 12]);
                d0 = fmaf(h0.x, wcol[k+0],  fmaf(h0.y, wcol[k+1],  fmaf(h0.z, wcol[k+2],  fmaf(h0.w, wcol[k+3],  d0))));
                d1 = fmaf(h1.x, wcol[k+4],  fmaf(h1.y, wcol[k+5],  fmaf(h1.z, wcol[k+6],  fmaf(h1.w, wcol[k+7],  d1))));
                d2 = fmaf(h2.x, wcol[k+8],  fmaf(h2.y, wcol[k+9],  fmaf(h2.z, wcol[k+10], fmaf(h2.w, wcol[k+11], d2))));
                d3 = fmaf(h3.x, wcol[k+12], fmaf(h3.y, wcol[k+13], fmaf(h3.z, wcol[k+14], fmaf(h3.w, wcol[k+15], d3))));
            }
            float wv = (d0 + d1) + (d2 + d3);

            // path-specific accumulate (warp-uniform branches)
            const float* ea = edge_attr + ed * 9;
            if (t < 64) {
                acc0 = fmaf(yv0 * __ldg(&ea[0]), wv, acc0);
            } else if (t < 128) {
                float b = yv0 * wv;
                acc0 = fmaf(b, __ldg(&ea[1]), acc0);
                acc1 = fmaf(b, __ldg(&ea[2]), acc1);
                acc2 = fmaf(b, __ldg(&ea[3]), acc2);
            } else if (t < 192) {
                float b = yv0 * wv;
                acc0 = fmaf(b, __ldg(&ea[4]), acc0);
                acc1 = fmaf(b, __ldg(&ea[5]), acc1);
                acc2 = fmaf(b, __ldg(&ea[6]), acc2);
                acc3 = fmaf(b, __ldg(&ea[7]), acc3);
                acc4 = fmaf(b, __ldg(&ea[8]), acc4);
            } else if (t < 224) {
                float b = __ldg(&ea[0]) * wv;
                acc0 = fmaf(b, yv0, acc0);
                acc1 = fmaf(b, yv1, acc1);
                acc2 = fmaf(b, yv2, acc2);
            } else if (t < 256) {
                float e1a = __ldg(&ea[1]), e1b = __ldg(&ea[2]), e1c = __ldg(&ea[3]);
                acc0 = fmaf(INV_S3 * wv, fmaf(yv0, e1a, fmaf(yv1, e1b, yv2 * e1c)), acc0);
            } else if (t < 288) {
                float e1a = __ldg(&ea[1]), e1b = __ldg(&ea[2]), e1c = __ldg(&ea[3]);
                float s = -wv;
                acc0 = fmaf(s, (yv2 * e1a + yv0 * e1c) * IS2, acc0);
                acc1 = fmaf(s, (yv0 * e1b + yv1 * e1a) * IS2, acc1);
                acc2 = fmaf(s, (-yv0 * e1a + 2.f * yv1 * e1b - yv2 * e1c) * IS6, acc2);
                acc3 = fmaf(s, (yv1 * e1c + yv2 * e1b) * IS2, acc3);
                acc4 = fmaf(s, (-yv0 * e1a + yv2 * e1c) * IS2, acc4);
            } else {
                float p0 = __ldg(&ea[4]), p1 = __ldg(&ea[5]), p2 = __ldg(&ea[6]);
                float p3 = __ldg(&ea[7]), p4 = __ldg(&ea[8]);
                float Myy = -p2 * IS6 - p4 * IS2;
                float Mzz =  2.f * p2 * IS6;
                float Mxx = -p2 * IS6 + p4 * IS2;
                float Myz =  p1 * IS2;
                float Myx =  p0 * IS2;
                float Mzx =  p3 * IS2;
                float s = S3_DIV_S5 * wv;
                acc0 = fmaf(s, fmaf(Myy, yv0, fmaf(Myz, yv1, Myx * yv2)), acc0);
                acc1 = fmaf(s, fmaf(Myz, yv0, fmaf(Mzz, yv1, Mzx * yv2)), acc1);
                acc2 = fmaf(s, fmaf(Myx, yv0, fmaf(Mzx, yv1, Mxx * yv2)), acc2);
            }

            // prefetch next y + compute next h
            float yn0 = 0.f, yn1 = 0.f, yn2 = 0.f;
            if (more) {
                if (t < 192) {
                    yn0 = __ldg(&g_y[src_n * 160 + (t & 63)]);
                } else {
                    const float* yp = &g_y[src_n * 160 + 64 + 3 * ((t - 192) & 31)];
                    yn0 = __ldg(yp); yn1 = __ldg(yp + 1); yn2 = __ldg(yp + 2);
                }
                if (t < 64) {
                    float z = 0.f;
                    #pragma unroll
                    for (int k = 0; k < 8; k++) z = fmaf(el_n[k], s_w0[k * 64 + t], z);
                    z *= INV_S8;
                    float sg = __fdividef(1.f, 1.f + __expf(-z));
                    hb[par ^ 1][t] = z * sg * (SILU_C_F * 0.03125f);
                }
            }
            __syncthreads();
            ed = ed_n; yv0 = yn0; yv1 = yn1; yv2 = yn2; par ^= 1;
        }
    }

    // stage accumulators into lin2-friendly smem layouts
    if (t < 64) {
        m[t] = acc0;
    } else if (t < 128) {
        int u = t - 64;
        m1T[u] = acc0; m1T[128 + u] = acc1; m1T[256 + u] = acc2;
    } else if (t < 192) {
        int u = t - 128;
        m2T[u] = acc0; m2T[96 + u] = acc1; m2T[192 + u] = acc2;
        m2T[288 + u] = acc3; m2T[384 + u] = acc4;
    } else if (t < 224) {
        int v = t - 192 + 64;
        m1T[v] = acc0; m1T[128 + v] = acc1; m1T[256 + v] = acc2;
    } else if (t < 256) {
        m[64 + (t - 224)] = acc0;
    } else if (t < 288) {
        int v = t - 256 + 64;
        m2T[v] = acc0; m2T[96 + v] = acc1; m2T[192 + v] = acc2;
        m2T[288 + v] = acc3; m2T[384 + v] = acc4;
    } else {
        int v = t - 288 + 96;
        m1T[v] = acc0; m1T[128 + v] = acc1; m1T[256 + v] = acc2;
    }
    __syncthreads();

    // lin2 + combine (constants folded into g_w*T and g_s)
    float a = node_attr[n];
    if (t < 64) {
        float o = 0.f;
        #pragma unroll
        for (int p = 0; p < 96; p += 4) {
            float4 mv = *reinterpret_cast<const float4*>(&m[p]);
            float4 wv = __ldg(reinterpret_cast<const float4*>(&g_w0T[t * 96 + p]));
            o = fmaf(mv.x, wv.x, fmaf(mv.y, wv.y, fmaf(mv.z, wv.z, fmaf(mv.w, wv.w, o))));
        }
        out[n * 320 + t] = __ldg(&g_s[n * 160 + t]) + o * a;
    } else if (t < 160) {
        int j = t - 64, v = j / 3, i = j - 3 * v;
        float o = 0.f;
        #pragma unroll
        for (int p = 0; p < 128; p += 4) {
            float4 mv = *reinterpret_cast<const float4*>(&m1T[i * 128 + p]);
            float4 wv = __ldg(reinterpret_cast<const float4*>(&g_w1T[v * 128 + p]));
            o = fmaf(mv.x, wv.x, fmaf(mv.y, wv.y, fmaf(mv.z, wv.z, fmaf(mv.w, wv.w, o))));
        }
        out[n * 320 + t] = __ldg(&g_s[n * 160 + t]) + o * a;
    } else {
        int j = t - 160, v = j / 5, i = j - 5 * v;
        float o = 0.f;
        #pragma unroll
        for (int p = 0; p < 96; p += 4) {
            float4 mv = *reinterpret_cast<const float4*>(&m2T[i * 96 + p]);
            float4 wv = __ldg(reinterpret_cast<const float4*>(&g_w2T[v * 96 + p]));
            o = fmaf(mv.x, wv.x, fmaf(mv.y, wv.y, fmaf(mv.z, wv.z, fmaf(mv.w, wv.w, o))));
        }
        out[n * 320 + t] = o * a;
    }
}

extern "C" void kernel_launch(void* const* d_in, const int* in_sizes, int n_in,
                              void* d_out, int out_size)
{
    const float* node_input = (const float*)d_in[0];
    const float* node_attr  = (const float*)d_in[1];
    const int*   edge_src   = (const int*)  d_in[2];
    const int*   edge_dst   = (const int*)  d_in[3];
    const float* edge_attr  = (const float*)d_in[4];
    const float* ele        = (const float*)d_in[5];
    const float* sc_w0      = (const float*)d_in[6];
    const float* sc_w1      = (const float*)d_in[7];
    const float* lin1_w0    = (const float*)d_in[8];
    const float* lin1_w1    = (const float*)d_in[9];
    const float* fc_w0      = (const float*)d_in[10];
    const float* fc_w1      = (const float*)d_in[11];
    const float* lin2_w0    = (const float*)d_in[12];
    const float* lin2_w1    = (const float*)d_in[13];
    const float* lin2_w2    = (const float*)d_in[14];
    float* out = (float*)d_out;

    k_zero<<<(NN + 255) / 256, 256>>>();
    k_tw<<<(23552 + 255) / 256, 256>>>(lin2_w0, lin2_w1, lin2_w2, lin1_w0, lin1_w1, sc_w0, sc_w1);
    k_hist<<<(NE + 255) / 256, 256>>>(edge_dst);
    k_scan<<<1, 512>>>();
    k_fill<<<(NE + 255) / 256, 256>>>(edge_dst);
    k_node<<<NN, 160>>>(node_input, node_attr);
    k_mega<<<NN, 320>>>(edge_attr, ele, edge_src, node_attr, fc_w1, fc_w0, out);
}

// round 9
// speedup vs baseline: 1.1980x; 1.1980x over previous
#include <cuda_runtime.h>

#define NN 10000
#define NE 160000

#define SILU_C_F   1.6765867f
#define INV_S8     0.35355339059327373f
#define INV_S32    0.17677669529663687f
#define INV_S96    0.10206207261596575f
#define INV_S128   0.08838834764831845f
#define INV_S3     0.57735026918962576f
#define S3_DIV_S5  0.77459666924148338f   // sqrt(3/5)
#define IS2        0.70710678118654752f   // 1/sqrt(2)
#define IS6        0.40824829046386302f   // 1/sqrt(6)
#define C_S        0.38268343236508977f   // sin(pi/8)
#define C_X        0.92387953251128676f   // cos(pi/8)

// scratch
__device__ float g_y[NN * 160];
__device__ float g_s[NN * 160];     // self-connection, C_S pre-folded
__device__ float g_w[NE * 320];     // per-edge TP weights (GEMM output)
// sort scratch
__device__ int g_count[NN];
__device__ int g_fill[NN];
__device__ int g_offset[NN + 1];
__device__ int g_perm[NE];
// transposed weights (norm constants folded)
__device__ float g_w0T[64 * 96];    // lin2_w0^T * C_X/sqrt(96)
__device__ float g_w1T[32 * 128];   // lin2_w1^T * C_X/sqrt(128)
__device__ float g_w2T[32 * 96];    // lin2_w2^T * 1/sqrt(96)
__device__ float g_l1w0T[64 * 64];
__device__ float g_scw0T[64 * 64];
__device__ float g_l1w1T[32 * 32];
__device__ float g_scw1T[32 * 32];

__device__ __forceinline__ unsigned long long pack2(float x) {
    unsigned long long r; asm("mov.b64 %0, {%1, %1};" : "=l"(r) : "f"(x)); return r;
}
__device__ __forceinline__ void fma2(unsigned long long& d, unsigned long long a, unsigned long long b) {
    asm("fma.rn.f32x2 %0, %1, %2, %0;" : "+l"(d) : "l"(a), "l"(b));
}
__device__ __forceinline__ float2 unpack2(unsigned long long v) {
    float2 f; asm("mov.b64 {%0, %1}, %2;" : "=f"(f.x), "=f"(f.y) : "l"(v)); return f;
}

// ---------------- zero counters ----------------
__global__ void k_zero() {
    int i = blockIdx.x * blockDim.x + threadIdx.x;
    if (i < NN) { g_count[i] = 0; g_fill[i] = 0; }
}

// ---------------- histogram / scan / permutation ----------------
__global__ void k_hist(const int* __restrict__ edge_dst) {
    int i = blockIdx.x * blockDim.x + threadIdx.x;
    if (i < NE) atomicAdd(&g_count[edge_dst[i]], 1);
}
__global__ __launch_bounds__(512) void k_scan() {
    __shared__ int part[512];
    int t = threadIdx.x;
    int base = t * 20;
    int s = 0;
    #pragma unroll
    for (int i = 0; i < 20; i++) { int idx = base + i; if (idx < NN) s += g_count[idx]; }
    part[t] = s;
    __syncthreads();
    for (int d = 1; d < 512; d <<= 1) {
        int v = (t >= d) ? part[t - d] : 0;
        __syncthreads();
        part[t] += v;
        __syncthreads();
    }
    int run = (t > 0) ? part[t - 1] : 0;
    for (int i = 0; i < 20; i++) {
        int idx = base + i;
        if (idx < NN) { g_offset[idx] = run; run += g_count[idx]; }
    }
    if (t == 511) g_offset[NN] = run;
}
__global__ void k_fill(const int* __restrict__ edge_dst) {
    int e = blockIdx.x * blockDim.x + threadIdx.x;
    if (e < NE) {
        int d = edge_dst[e];
        int p = atomicAdd(&g_fill[d], 1);
        g_perm[g_offset[d] + p] = e;
    }
}

// ---------------- transpose weights (fold output constants) ----------------
__global__ void k_tw(const float* __restrict__ lin2_w0, const float* __restrict__ lin2_w1,
                     const float* __restrict__ lin2_w2, const float* __restrict__ lin1_w0,
                     const float* __restrict__ lin1_w1, const float* __restrict__ sc_w0,
                     const float* __restrict__ sc_w1) {
    int idx = blockIdx.x * blockDim.x + threadIdx.x;
    if (idx < 6144) { int c = idx / 96, p = idx % 96;
        g_w0T[idx] = lin2_w0[p * 64 + c] * (C_X * INV_S96); return; }
    idx -= 6144;
    if (idx < 4096) { int c = idx / 128, p = idx % 128;
        g_w1T[idx] = lin2_w1[p * 32 + c] * (C_X * INV_S128); return; }
    idx -= 4096;
    if (idx < 3072) { int c = idx / 96, p = idx % 96;
        g_w2T[idx] = lin2_w2[p * 32 + c] * INV_S96; return; }
    idx -= 3072;
    if (idx < 4096) { int c = idx / 64, u = idx % 64; g_l1w0T[idx] = lin1_w0[u * 64 + c]; return; }
    idx -= 4096;
    if (idx < 4096) { int c = idx / 64, u = idx % 64; g_scw0T[idx] = sc_w0[u * 64 + c]; return; }
    idx -= 4096;
    if (idx < 1024) { int c = idx / 32, u = idx % 32; g_l1w1T[idx] = lin1_w1[u * 32 + c]; return; }
    idx -= 1024;
    if (idx < 1024) { int c = idx / 32, u = idx % 32; g_scw1T[idx] = sc_w1[u * 32 + c]; return; }
}

// ---------------- node pre-linear ----------------
__global__ __launch_bounds__(160) void k_node(
    const float* __restrict__ node_input, const float* __restrict__ node_attr)
{
    __shared__ float xs[160];
    __shared__ float xsT[96];
    int n = blockIdx.x, t = threadIdx.x;
    xs[t] = node_input[n * 160 + t];
    __syncthreads();
    if (t < 96) { int i = t >> 5, u = t & 31; xsT[t] = xs[64 + u * 3 + i]; }
    __syncthreads();
    float a = node_attr[n];
    if (t < 64) {
        float ay = 0.f, as = 0.f;
        #pragma unroll
        for (int u = 0; u < 64; u += 4) {
            float4 xv = *reinterpret_cast<const float4*>(xs + u);
            float4 wy = *reinterpret_cast<const float4*>(g_l1w0T + t * 64 + u);
            float4 ws = *reinterpret_cast<const float4*>(g_scw0T + t * 64 + u);
            ay = fmaf(xv.x, wy.x, fmaf(xv.y, wy.y, fmaf(xv.z, wy.z, fmaf(xv.w, wy.w, ay))));
            as = fmaf(xv.x, ws.x, fmaf(xv.y, ws.y, fmaf(xv.z, ws.z, fmaf(xv.w, ws.w, as))));
        }
        g_y[n * 160 + t] = ay * a * 0.125f;
        g_s[n * 160 + t] = as * a * (0.125f * C_S);
    } else {
        int j = t - 64, v = j / 3, i = j - 3 * v;
        float ay = 0.f, as = 0.f;
        #pragma unroll
        for (int u = 0; u < 32; u += 4) {
            float4 xv = *reinterpret_cast<const float4*>(xsT + i * 32 + u);
            float4 wy = *reinterpret_cast<const float4*>(g_l1w1T + v * 32 + u);
            float4 ws = *reinterpret_cast<const float4*>(g_scw1T + v * 32 + u);
            ay = fmaf(xv.x, wy.x, fmaf(xv.y, wy.y, fmaf(xv.z, wy.z, fmaf(xv.w, wy.w, ay))));
            as = fmaf(xv.x, ws.x, fmaf(xv.y, ws.y, fmaf(xv.z, ws.z, fmaf(xv.w, ws.w, as))));
        }
        g_y[n * 160 + t] = ay * a * INV_S32;
        g_s[n * 160 + t] = as * a * (INV_S32 * C_S);
    }
}

// ---------------- GEMM: W[e][t] = silu-MLP(ele[e]) . fc_w1[:,t] ----------------
// block = 16 edges x 320 cols; thread t owns col t; fc_w1 col in regs (2 halves);
// h staged transposed in smem; inner loop = broadcast LDS.128 + fma.rn.f32x2.
#define GE 16
__global__ __launch_bounds__(320, 2) void k_gemm(
    const float* __restrict__ ele, const float* __restrict__ fc_w0,
    const float* __restrict__ fc_w1)
{
    __shared__ float s_el[GE * 8];
    __shared__ float s_w0[512];
    __shared__ float sHT[64 * GE];   // sHT[c*16 + e]
    int t = threadIdx.x;
    int e0 = blockIdx.x * GE;

    if (t < GE * 8) s_el[t] = ele[e0 * 8 + t];
    for (int i = t; i < 512; i += 320) s_w0[i] = fc_w0[i];
    __syncthreads();

    // H compute: thread t<256 handles c = t>>2, edges e = (t&3) + 4j
    if (t < 256) {
        int c = t >> 2, m = t & 3;
        #pragma unroll
        for (int j = 0; j < 4; j++) {
            int e = m + 4 * j;
            float z = 0.f;
            #pragma unroll
            for (int k = 0; k < 8; k++) z = fmaf(s_el[e * 8 + k], s_w0[k * 64 + c], z);
            z *= INV_S8;
            float sg = __fdividef(1.f, 1.f + __expf(-z));
            sHT[c * GE + e] = z * sg * (SILU_C_F * 0.03125f);
        }
    }
    __syncthreads();

    unsigned long long acc[8];
    #pragma unroll
    for (int j = 0; j < 8; j++) acc[j] = 0ULL;

    #pragma unroll 1
    for (int half = 0; half < 2; half++) {
        float wcol[32];
        #pragma unroll
        for (int k = 0; k < 32; k++) wcol[k] = __ldg(&fc_w1[(half * 32 + k) * 320 + t]);
        const float* hb = sHT + half * 32 * GE;
        #pragma unroll
        for (int k = 0; k < 32; k++) {
            unsigned long long wk = pack2(wcol[k]);
            const ulonglong2* hp = reinterpret_cast<const ulonglong2*>(hb + k * GE);
            ulonglong2 ha = hp[0], hc = hp[1];
            fma2(acc[0], ha.x, wk); fma2(acc[1], ha.y, wk);
            fma2(acc[2], hc.x, wk); fma2(acc[3], hc.y, wk);
            ulonglong2 hd = hp[2], he = hp[3];
            fma2(acc[4], hd.x, wk); fma2(acc[5], hd.y, wk);
            fma2(acc[6], he.x, wk); fma2(acc[7], he.y, wk);
        }
    }

    #pragma unroll
    for (int j = 0; j < 8; j++) {
        float2 v = unpack2(acc[j]);
        g_w[(e0 + 2 * j) * 320 + t] = v.x;
        g_w[(e0 + 2 * j + 1) * 320 + t] = v.y;
    }
}

// ---------------- gather: per dst node, no atomics, no per-edge syncs ----------------
// thread t ownership (same as R8, verified correct):
//   [0,64): k0  | [64,128): k2  | [128,192): k5 | [192,224): k3
//   [224,256): k1 | [256,288): k6 | [288,320): k4
__global__ __launch_bounds__(320) void k_gather(
    const float* __restrict__ edge_attr, const int* __restrict__ edge_src,
    const float* __restrict__ node_attr, float* __restrict__ out)
{
    __shared__ float m[96];
    __shared__ float m1T[3 * 128];
    __shared__ float m2T[5 * 96];

    int n = blockIdx.x, t = threadIdx.x;
    int off = g_offset[n];
    int deg = g_offset[n + 1] - off;
    float acc0 = 0.f, acc1 = 0.f, acc2 = 0.f, acc3 = 0.f, acc4 = 0.f;

    int ed = (deg > 0) ? __ldg(&g_perm[off]) : 0;
    int src = (deg > 0) ? __ldg(&edge_src[ed]) : 0;

    for (int i = 0; i < deg; i++) {
        // prefetch next edge's indices (hides perm->src chain)
        int ed_n = (i + 1 < deg) ? __ldg(&g_perm[off + i + 1]) : 0;

        float wv = __ldg(&g_w[ed * 320 + t]);
        float yv0, yv1 = 0.f, yv2 = 0.f;
        if (t < 192) {
            yv0 = __ldg(&g_y[src * 160 + (t & 63)]);
        } else {
            const float* yp = &g_y[src * 160 + 64 + 3 * ((t - 192) & 31)];
            yv0 = __ldg(yp); yv1 = __ldg(yp + 1); yv2 = __ldg(yp + 2);
        }
        int src_n = (i + 1 < deg) ? __ldg(&edge_src[ed_n]) : 0;
        const float* ea = edge_attr + ed * 9;

        if (t < 64) {
            acc0 = fmaf(yv0 * __ldg(&ea[0]), wv, acc0);
        } else if (t < 128) {
            float b = yv0 * wv;
            acc0 = fmaf(b, __ldg(&ea[1]), acc0);
            acc1 = fmaf(b, __ldg(&ea[2]), acc1);
            acc2 = fmaf(b, __ldg(&ea[3]), acc2);
        } else if (t < 192) {
            float b = yv0 * wv;
            acc0 = fmaf(b, __ldg(&ea[4]), acc0);
            acc1 = fmaf(b, __ldg(&ea[5]), acc1);
            acc2 = fmaf(b, __ldg(&ea[6]), acc2);
            acc3 = fmaf(b, __ldg(&ea[7]), acc3);
            acc4 = fmaf(b, __ldg(&ea[8]), acc4);
        } else if (t < 224) {
            float b = __ldg(&ea[0]) * wv;
            acc0 = fmaf(b, yv0, acc0);
            acc1 = fmaf(b, yv1, acc1);
            acc2 = fmaf(b, yv2, acc2);
        } else if (t < 256) {
            float e1a = __ldg(&ea[1]), e1b = __ldg(&ea[2]), e1c = __ldg(&ea[3]);
            acc0 = fmaf(INV_S3 * wv, fmaf(yv0, e1a, fmaf(yv1, e1b, yv2 * e1c)), acc0);
        } else if (t < 288) {
            float e1a = __ldg(&ea[1]), e1b = __ldg(&ea[2]), e1c = __ldg(&ea[3]);
            float s = -wv;
            acc0 = fmaf(s, (yv2 * e1a + yv0 * e1c) * IS2, acc0);
            acc1 = fmaf(s, (yv0 * e1b + yv1 * e1a) * IS2, acc1);
            acc2 = fmaf(s, (-yv0 * e1a + 2.f * yv1 * e1b - yv2 * e1c) * IS6, acc2);
            acc3 = fmaf(s, (yv1 * e1c + yv2 * e1b) * IS2, acc3);
            acc4 = fmaf(s, (-yv0 * e1a + yv2 * e1c) * IS2, acc4);
        } else {
            float p0 = __ldg(&ea[4]), p1 = __ldg(&ea[5]), p2 = __ldg(&ea[6]);
            float p3 = __ldg(&ea[7]), p4 = __ldg(&ea[8]);
            float Myy = -p2 * IS6 - p4 * IS2;
            float Mzz =  2.f * p2 * IS6;
            float Mxx = -p2 * IS6 + p4 * IS2;
            float Myz =  p1 * IS2;
            float Myx =  p0 * IS2;
            float Mzx =  p3 * IS2;
            float s = S3_DIV_S5 * wv;
            acc0 = fmaf(s, fmaf(Myy, yv0, fmaf(Myz, yv1, Myx * yv2)), acc0);
            acc1 = fmaf(s, fmaf(Myz, yv0, fmaf(Mzz, yv1, Mzx * yv2)), acc1);
            acc2 = fmaf(s, fmaf(Myx, yv0, fmaf(Mzx, yv1, Mxx * yv2)), acc2);
        }
        ed = ed_n; src = src_n;
    }

    // stage accumulators into lin2-friendly smem layouts
    if (t < 64) {
        m[t] = acc0;
    } else if (t < 128) {
        int u = t - 64;
        m1T[u] = acc0; m1T[128 + u] = acc1; m1T[256 + u] = acc2;
    } else if (t < 192) {
        int u = t - 128;
        m2T[u] = acc0; m2T[96 + u] = acc1; m2T[192 + u] = acc2;
        m2T[288 + u] = acc3; m2T[384 + u] = acc4;
    } else if (t < 224) {
        int v = t - 192 + 64;
        m1T[v] = acc0; m1T[128 + v] = acc1; m1T[256 + v] = acc2;
    } else if (t < 256) {
        m[64 + (t - 224)] = acc0;
    } else if (t < 288) {
        int v = t - 256 + 64;
        m2T[v] = acc0; m2T[96 + v] = acc1; m2T[192 + v] = acc2;
        m2T[288 + v] = acc3; m2T[384 + v] = acc4;
    } else {
        int v = t - 288 + 96;
        m1T[v] = acc0; m1T[128 + v] = acc1; m1T[256 + v] = acc2;
    }
    __syncthreads();

    // lin2 + combine (constants folded into g_w*T and g_s)
    float a = node_attr[n];
    if (t < 64) {
        float o = 0.f;
        #pragma unroll
        for (int p = 0; p < 96; p += 4) {
            float4 mv = *reinterpret_cast<const float4*>(&m[p]);
            float4 wv = __ldg(reinterpret_cast<const float4*>(&g_w0T[t * 96 + p]));
            o = fmaf(mv.x, wv.x, fmaf(mv.y, wv.y, fmaf(mv.z, wv.z, fmaf(mv.w, wv.w, o))));
        }
        out[n * 320 + t] = __ldg(&g_s[n * 160 + t]) + o * a;
    } else if (t < 160) {
        int j = t - 64, v = j / 3, i = j - 3 * v;
        float o = 0.f;
        #pragma unroll
        for (int p = 0; p < 128; p += 4) {
            float4 mv = *reinterpret_cast<const float4*>(&m1T[i * 128 + p]);
            float4 wv = __ldg(reinterpret_cast<const float4*>(&g_w1T[v * 128 + p]));
            o = fmaf(mv.x, wv.x, fmaf(mv.y, wv.y, fmaf(mv.z, wv.z, fmaf(mv.w, wv.w, o))));
        }
        out[n * 320 + t] = __ldg(&g_s[n * 160 + t]) + o * a;
    } else {
        int j = t - 160, v = j / 5, i = j - 5 * v;
        float o = 0.f;
        #pragma unroll
        for (int p = 0; p < 96; p += 4) {
            float4 mv = *reinterpret_cast<const float4*>(&m2T[i * 96 + p]);
            float4 wv = __ldg(reinterpret_cast<const float4*>(&g_w2T[v * 96 + p]));
            o = fmaf(mv.x, wv.x, fmaf(mv.y, wv.y, fmaf(mv.z, wv.z, fmaf(mv.w, wv.w, o))));
        }
        out[n * 320 + t] = o * a;
    }
}

extern "C" void kernel_launch(void* const* d_in, const int* in_sizes, int n_in,
                              void* d_out, int out_size)
{
    const float* node_input = (const float*)d_in[0];
    const float* node_attr  = (const float*)d_in[1];
    const int*   edge_src   = (const int*)  d_in[2];
    const int*   edge_dst   = (const int*)  d_in[3];
    const float* edge_attr  = (const float*)d_in[4];
    const float* ele        = (const float*)d_in[5];
    const float* sc_w0      = (const float*)d_in[6];
    const float* sc_w1      = (const float*)d_in[7];
    const float* lin1_w0    = (const float*)d_in[8];
    const float* lin1_w1    = (const float*)d_in[9];
    const float* fc_w0      = (const float*)d_in[10];
    const float* fc_w1      = (const float*)d_in[11];
    const float* lin2_w0    = (const float*)d_in[12];
    const float* lin2_w1    = (const float*)d_in[13];
    const float* lin2_w2    = (const float*)d_in[14];
    float* out = (float*)d_out;

    // order chosen so k_gemm is the 6th launch (ncu -s 5 -c 1 captures it)
    k_zero<<<(NN + 255) / 256, 256>>>();
    k_tw<<<(23552 + 255) / 256, 256>>>(lin2_w0, lin2_w1, lin2_w2, lin1_w0, lin1_w1, sc_w0, sc_w1);
    k_hist<<<(NE + 255) / 256, 256>>>(edge_dst);
    k_scan<<<1, 512>>>();
    k_node<<<NN, 160>>>(node_input, node_attr);
    k_gemm<<<NE / GE, 320>>>(ele, fc_w0, fc_w1);
    k_fill<<<(NE + 255) / 256, 256>>>(edge_dst);
    k_gather<<<NN, 320>>>(edge_attr, edge_src, node_attr, out);
}

// round 10
// speedup vs baseline: 1.2204x; 1.0187x over previous
#include <cuda_runtime.h>

#define NN 10000
#define NE 160000

#define SILU_C_F   1.6765867f
#define INV_S8     0.35355339059327373f
#define INV_S32    0.17677669529663687f
#define INV_S96    0.10206207261596575f
#define INV_S128   0.08838834764831845f
#define INV_S3     0.57735026918962576f
#define S3_DIV_S5  0.77459666924148338f   // sqrt(3/5)
#define IS2        0.70710678118654752f   // 1/sqrt(2)
#define IS6        0.40824829046386302f   // 1/sqrt(6)
#define C_S        0.38268343236508977f   // sin(pi/8)
#define C_X        0.92387953251128676f   // cos(pi/8)

// scratch
__device__ float g_y[NN * 160];
__device__ float g_s[NN * 160];     // self-connection, C_S pre-folded
__device__ float g_w[NE * 320];     // per-edge TP weights (GEMM output)
// sort scratch
__device__ int g_count[NN];
__device__ int g_fill[NN];
__device__ int g_offset[NN + 1];
__device__ int g_perm[NE];
// transposed weights (norm constants folded)
__device__ float g_w0T[64 * 96];    // lin2_w0^T * C_X/sqrt(96)
__device__ float g_w1T[32 * 128];   // lin2_w1^T * C_X/sqrt(128)
__device__ float g_w2T[32 * 96];    // lin2_w2^T * 1/sqrt(96)
__device__ float g_l1w0T[64 * 64];
__device__ float g_scw0T[64 * 64];
__device__ float g_l1w1T[32 * 32];
__device__ float g_scw1T[32 * 32];

__device__ __forceinline__ unsigned long long pack2(float x) {
    unsigned long long r; asm("mov.b64 %0, {%1, %1};" : "=l"(r) : "f"(x)); return r;
}
__device__ __forceinline__ void fma2(unsigned long long& d, unsigned long long a, unsigned long long b) {
    asm("fma.rn.f32x2 %0, %1, %2, %0;" : "+l"(d) : "l"(a), "l"(b));
}
__device__ __forceinline__ float2 unpack2(unsigned long long v) {
    float2 f; asm("mov.b64 {%0, %1}, %2;" : "=f"(f.x), "=f"(f.y) : "l"(v)); return f;
}

// ---------------- zero counters ----------------
__global__ void k_zero() {
    int i = blockIdx.x * blockDim.x + threadIdx.x;
    if (i < NN) { g_count[i] = 0; g_fill[i] = 0; }
}

// ---------------- histogram / scan / permutation ----------------
__global__ void k_hist(const int* __restrict__ edge_dst) {
    int i = blockIdx.x * blockDim.x + threadIdx.x;
    if (i < NE) atomicAdd(&g_count[edge_dst[i]], 1);
}
__global__ __launch_bounds__(512) void k_scan() {
    __shared__ int part[512];
    int t = threadIdx.x;
    int base = t * 20;
    int s = 0;
    #pragma unroll
    for (int i = 0; i < 20; i++) { int idx = base + i; if (idx < NN) s += g_count[idx]; }
    part[t] = s;
    __syncthreads();
    for (int d = 1; d < 512; d <<= 1) {
        int v = (t >= d) ? part[t - d] : 0;
        __syncthreads();
        part[t] += v;
        __syncthreads();
    }
    int run = (t > 0) ? part[t - 1] : 0;
    for (int i = 0; i < 20; i++) {
        int idx = base + i;
        if (idx < NN) { g_offset[idx] = run; run += g_count[idx]; }
    }
    if (t == 511) g_offset[NN] = run;
}
__global__ void k_fill(const int* __restrict__ edge_dst) {
    int e = blockIdx.x * blockDim.x + threadIdx.x;
    if (e < NE) {
        int d = edge_dst[e];
        int p = atomicAdd(&g_fill[d], 1);
        g_perm[g_offset[d] + p] = e;
    }
}

// ---------------- transpose weights (fold output constants) ----------------
__global__ void k_tw(const float* __restrict__ lin2_w0, const float* __restrict__ lin2_w1,
                     const float* __restrict__ lin2_w2, const float* __restrict__ lin1_w0,
                     const float* __restrict__ lin1_w1, const float* __restrict__ sc_w0,
                     const float* __restrict__ sc_w1) {
    int idx = blockIdx.x * blockDim.x + threadIdx.x;
    if (idx < 6144) { int c = idx / 96, p = idx % 96;
        g_w0T[idx] = lin2_w0[p * 64 + c] * (C_X * INV_S96); return; }
    idx -= 6144;
    if (idx < 4096) { int c = idx / 128, p = idx % 128;
        g_w1T[idx] = lin2_w1[p * 32 + c] * (C_X * INV_S128); return; }
    idx -= 4096;
    if (idx < 3072) { int c = idx / 96, p = idx % 96;
        g_w2T[idx] = lin2_w2[p * 32 + c] * INV_S96; return; }
    idx -= 3072;
    if (idx < 4096) { int c = idx / 64, u = idx % 64; g_l1w0T[idx] = lin1_w0[u * 64 + c]; return; }
    idx -= 4096;
    if (idx < 4096) { int c = idx / 64, u = idx % 64; g_scw0T[idx] = sc_w0[u * 64 + c]; return; }
    idx -= 4096;
    if (idx < 1024) { int c = idx / 32, u = idx % 32; g_l1w1T[idx] = lin1_w1[u * 32 + c]; return; }
    idx -= 1024;
    if (idx < 1024) { int c = idx / 32, u = idx % 32; g_scw1T[idx] = sc_w1[u * 32 + c]; return; }
}

// ---------------- node pre-linear ----------------
__global__ __launch_bounds__(160) void k_node(
    const float* __restrict__ node_input, const float* __restrict__ node_attr)
{
    __shared__ float xs[160];
    __shared__ float xsT[96];
    int n = blockIdx.x, t = threadIdx.x;
    xs[t] = node_input[n * 160 + t];
    __syncthreads();
    if (t < 96) { int i = t >> 5, u = t & 31; xsT[t] = xs[64 + u * 3 + i]; }
    __syncthreads();
    float a = node_attr[n];
    if (t < 64) {
        float ay = 0.f, as = 0.f;
        #pragma unroll
        for (int u = 0; u < 64; u += 4) {
            float4 xv = *reinterpret_cast<const float4*>(xs + u);
            float4 wy = *reinterpret_cast<const float4*>(g_l1w0T + t * 64 + u);
            float4 ws = *reinterpret_cast<const float4*>(g_scw0T + t * 64 + u);
            ay = fmaf(xv.x, wy.x, fmaf(xv.y, wy.y, fmaf(xv.z, wy.z, fmaf(xv.w, wy.w, ay))));
            as = fmaf(xv.x, ws.x, fmaf(xv.y, ws.y, fmaf(xv.z, ws.z, fmaf(xv.w, ws.w, as))));
        }
        g_y[n * 160 + t] = ay * a * 0.125f;
        g_s[n * 160 + t] = as * a * (0.125f * C_S);
    } else {
        int j = t - 64, v = j / 3, i = j - 3 * v;
        float ay = 0.f, as = 0.f;
        #pragma unroll
        for (int u = 0; u < 32; u += 4) {
            float4 xv = *reinterpret_cast<const float4*>(xsT + i * 32 + u);
            float4 wy = *reinterpret_cast<const float4*>(g_l1w1T + v * 32 + u);
            float4 ws = *reinterpret_cast<const float4*>(g_scw1T + v * 32 + u);
            ay = fmaf(xv.x, wy.x, fmaf(xv.y, wy.y, fmaf(xv.z, wy.z, fmaf(xv.w, wy.w, ay))));
            as = fmaf(xv.x, ws.x, fmaf(xv.y, ws.y, fmaf(xv.z, ws.z, fmaf(xv.w, ws.w, as))));
        }
        g_y[n * 160 + t] = ay * a * INV_S32;
        g_s[n * 160 + t] = as * a * (INV_S32 * C_S);
    }
}

// ---------------- GEMM: W[e][t] = silu-MLP(ele[e]) . fc_w1[:,t] ----------------
#define GE 16
__global__ __launch_bounds__(320, 2) void k_gemm(
    const float* __restrict__ ele, const float* __restrict__ fc_w0,
    const float* __restrict__ fc_w1)
{
    __shared__ float s_el[GE * 8];
    __shared__ float s_w0[512];
    __shared__ float sHT[64 * GE];   // sHT[c*16 + e]
    int t = threadIdx.x;
    int e0 = blockIdx.x * GE;

    if (t < GE * 8) s_el[t] = ele[e0 * 8 + t];
    for (int i = t; i < 512; i += 320) s_w0[i] = fc_w0[i];
    __syncthreads();

    if (t < 256) {
        int c = t >> 2, m = t & 3;
        #pragma unroll
        for (int j = 0; j < 4; j++) {
            int e = m + 4 * j;
            float z = 0.f;
            #pragma unroll
            for (int k = 0; k < 8; k++) z = fmaf(s_el[e * 8 + k], s_w0[k * 64 + c], z);
            z *= INV_S8;
            float sg = __fdividef(1.f, 1.f + __expf(-z));
            sHT[c * GE + e] = z * sg * (SILU_C_F * 0.03125f);
        }
    }
    __syncthreads();

    unsigned long long acc[8];
    #pragma unroll
    for (int j = 0; j < 8; j++) acc[j] = 0ULL;

    #pragma unroll 1
    for (int half = 0; half < 2; half++) {
        float wcol[32];
        #pragma unroll
        for (int k = 0; k < 32; k++) wcol[k] = __ldg(&fc_w1[(half * 32 + k) * 320 + t]);
        const float* hb = sHT + half * 32 * GE;
        #pragma unroll
        for (int k = 0; k < 32; k++) {
            unsigned long long wk = pack2(wcol[k]);
            const ulonglong2* hp = reinterpret_cast<const ulonglong2*>(hb + k * GE);
            ulonglong2 ha = hp[0], hc = hp[1];
            fma2(acc[0], ha.x, wk); fma2(acc[1], ha.y, wk);
            fma2(acc[2], hc.x, wk); fma2(acc[3], hc.y, wk);
            ulonglong2 hd = hp[2], he = hp[3];
            fma2(acc[4], hd.x, wk); fma2(acc[5], hd.y, wk);
            fma2(acc[6], he.x, wk); fma2(acc[7], he.y, wk);
        }
    }

    #pragma unroll
    for (int j = 0; j < 8; j++) {
        float2 v = unpack2(acc[j]);
        g_w[(e0 + 2 * j) * 320 + t] = v.x;
        g_w[(e0 + 2 * j + 1) * 320 + t] = v.y;
    }
}

// ---------------- gather: per dst node; smem-staged indices + depth-1 prefetch ----------------
// thread t ownership (verified):
//   [0,64): k0  | [64,128): k2  | [128,192): k5 | [192,224): k3
//   [224,256): k1 | [256,288): k6 | [288,320): k4
__global__ __launch_bounds__(320) void k_gather(
    const float* __restrict__ edge_attr, const int* __restrict__ edge_src,
    const float* __restrict__ node_attr, float* __restrict__ out)
{
    __shared__ float m[96];
    __shared__ float m1T[3 * 128];
    __shared__ float m2T[5 * 96];
    __shared__ int sed[64];
    __shared__ int ssrc[64];

    int n = blockIdx.x, t = threadIdx.x;
    int off = g_offset[n];
    int degAll = g_offset[n + 1] - off;
    float acc0 = 0.f, acc1 = 0.f, acc2 = 0.f, acc3 = 0.f, acc4 = 0.f;

    // region-specific edge_attr prefetch window
    int eabase, ean;
    if      (t < 64)  { eabase = 0; ean = 1; }
    else if (t < 128) { eabase = 1; ean = 3; }
    else if (t < 192) { eabase = 4; ean = 5; }
    else if (t < 224) { eabase = 0; ean = 1; }
    else if (t < 288) { eabase = 1; ean = 3; }
    else              { eabase = 4; ean = 5; }

    for (int tile = 0; tile < degAll; tile += 64) {
        int deg = degAll - tile; if (deg > 64) deg = 64;
        __syncthreads();
        if (t < deg) {
            int e = __ldg(&g_perm[off + tile + t]);
            sed[t] = e;
            ssrc[t] = __ldg(&edge_src[e]);
        }
        __syncthreads();

        // prologue: load tile edge 0
        int ed = sed[0], src = ssrc[0];
        float wv = __ldg(&g_w[ed * 320 + t]);
        float y0, y1 = 0.f, y2 = 0.f;
        if (t < 192) y0 = __ldg(&g_y[src * 160 + (t & 63)]);
        else { const float* yp = &g_y[src * 160 + 64 + 3 * ((t - 192) & 31)];
               y0 = __ldg(yp); y1 = __ldg(yp + 1); y2 = __ldg(yp + 2); }
        float er[5];
        #pragma unroll
        for (int j = 0; j < 5; j++) er[j] = (j < ean) ? __ldg(&edge_attr[ed * 9 + eabase + j]) : 0.f;

        for (int i = 0; i < deg; i++) {
            // issue next edge's loads first (no index chain — indices in smem)
            float wv_n = 0.f, y0_n = 0.f, y1_n = 0.f, y2_n = 0.f;
            float er_n[5] = {0.f, 0.f, 0.f, 0.f, 0.f};
            if (i + 1 < deg) {
                int edn = sed[i + 1], srcn = ssrc[i + 1];
                wv_n = __ldg(&g_w[edn * 320 + t]);
                if (t < 192) y0_n = __ldg(&g_y[srcn * 160 + (t & 63)]);
                else { const float* yp = &g_y[srcn * 160 + 64 + 3 * ((t - 192) & 31)];
                       y0_n = __ldg(yp); y1_n = __ldg(yp + 1); y2_n = __ldg(yp + 2); }
                #pragma unroll
                for (int j = 0; j < 5; j++) if (j < ean) er_n[j] = __ldg(&edge_attr[edn * 9 + eabase + j]);
            }

            if (t < 64) {
                acc0 = fmaf(y0 * er[0], wv, acc0);
            } else if (t < 128) {
                float b = y0 * wv;
                acc0 = fmaf(b, er[0], acc0); acc1 = fmaf(b, er[1], acc1); acc2 = fmaf(b, er[2], acc2);
            } else if (t < 192) {
                float b = y0 * wv;
                acc0 = fmaf(b, er[0], acc0); acc1 = fmaf(b, er[1], acc1); acc2 = fmaf(b, er[2], acc2);
                acc3 = fmaf(b, er[3], acc3); acc4 = fmaf(b, er[4], acc4);
            } else if (t < 224) {
                float b = er[0] * wv;
                acc0 = fmaf(b, y0, acc0); acc1 = fmaf(b, y1, acc1); acc2 = fmaf(b, y2, acc2);
            } else if (t < 256) {
                acc0 = fmaf(INV_S3 * wv, fmaf(y0, er[0], fmaf(y1, er[1], y2 * er[2])), acc0);
            } else if (t < 288) {
                float s = -wv;
                acc0 = fmaf(s, (y2 * er[0] + y0 * er[2]) * IS2, acc0);
                acc1 = fmaf(s, (y0 * er[1] + y1 * er[0]) * IS2, acc1);
                acc2 = fmaf(s, (-y0 * er[0] + 2.f * y1 * er[1] - y2 * er[2]) * IS6, acc2);
                acc3 = fmaf(s, (y1 * er[2] + y2 * er[1]) * IS2, acc3);
                acc4 = fmaf(s, (-y0 * er[0] + y2 * er[2]) * IS2, acc4);
            } else {
                float p0 = er[0], p1 = er[1], p2 = er[2], p3 = er[3], p4 = er[4];
                float Myy = -p2 * IS6 - p4 * IS2;
                float Mzz =  2.f * p2 * IS6;
                float Mxx = -p2 * IS6 + p4 * IS2;
                float Myz =  p1 * IS2;
                float Myx =  p0 * IS2;
                float Mzx =  p3 * IS2;
                float s = S3_DIV_S5 * wv;
                acc0 = fmaf(s, fmaf(Myy, y0, fmaf(Myz, y1, Myx * y2)), acc0);
                acc1 = fmaf(s, fmaf(Myz, y0, fmaf(Mzz, y1, Mzx * y2)), acc1);
                acc2 = fmaf(s, fmaf(Myx, y0, fmaf(Mzx, y1, Mxx * y2)), acc2);
            }
            wv = wv_n; y0 = y0_n; y1 = y1_n; y2 = y2_n;
            #pragma unroll
            for (int j = 0; j < 5; j++) er[j] = er_n[j];
        }
    }

    // stage accumulators into lin2-friendly smem layouts
    if (t < 64) {
        m[t] = acc0;
    } else if (t < 128) {
        int u = t - 64;
        m1T[u] = acc0; m1T[128 + u] = acc1; m1T[256 + u] = acc2;
    } else if (t < 192) {
        int u = t - 128;
        m2T[u] = acc0; m2T[96 + u] = acc1; m2T[192 + u] = acc2;
        m2T[288 + u] = acc3; m2T[384 + u] = acc4;
    } else if (t < 224) {
        int v = t - 192 + 64;
        m1T[v] = acc0; m1T[128 + v] = acc1; m1T[256 + v] = acc2;
    } else if (t < 256) {
        m[64 + (t - 224)] = acc0;
    } else if (t < 288) {
        int v = t - 256 + 64;
        m2T[v] = acc0; m2T[96 + v] = acc1; m2T[192 + v] = acc2;
        m2T[288 + v] = acc3; m2T[384 + v] = acc4;
    } else {
        int v = t - 288 + 96;
        m1T[v] = acc0; m1T[128 + v] = acc1; m1T[256 + v] = acc2;
    }
    __syncthreads();

    // lin2 + combine (constants folded into g_w*T and g_s)
    float a = node_attr[n];
    if (t < 64) {
        float o = 0.f;
        #pragma unroll
        for (int p = 0; p < 96; p += 4) {
            float4 mv = *reinterpret_cast<const float4*>(&m[p]);
            float4 wv4 = __ldg(reinterpret_cast<const float4*>(&g_w0T[t * 96 + p]));
            o = fmaf(mv.x, wv4.x, fmaf(mv.y, wv4.y, fmaf(mv.z, wv4.z, fmaf(mv.w, wv4.w, o))));
        }
        out[n * 320 + t] = __ldg(&g_s[n * 160 + t]) + o * a;
    } else if (t < 160) {
        int j = t - 64, v = j / 3, i = j - 3 * v;
        float o = 0.f;
        #pragma unroll
        for (int p = 0; p < 128; p += 4) {
            float4 mv = *reinterpret_cast<const float4*>(&m1T[i * 128 + p]);
            float4 wv4 = __ldg(reinterpret_cast<const float4*>(&g_w1T[v * 128 + p]));
            o = fmaf(mv.x, wv4.x, fmaf(mv.y, wv4.y, fmaf(mv.z, wv4.z, fmaf(mv.w, wv4.w, o))));
        }
        out[n * 320 + t] = __ldg(&g_s[n * 160 + t]) + o * a;
    } else {
        int j = t - 160, v = j / 5, i = j - 5 * v;
        float o = 0.f;
        #pragma unroll
        for (int p = 0; p < 96; p += 4) {
            float4 mv = *reinterpret_cast<const float4*>(&m2T[i * 96 + p]);
            float4 wv4 = __ldg(reinterpret_cast<const float4*>(&g_w2T[v * 96 + p]));
            o = fmaf(mv.x, wv4.x, fmaf(mv.y, wv4.y, fmaf(mv.z, wv4.z, fmaf(mv.w, wv4.w, o))));
        }
        out[n * 320 + t] = o * a;
    }
}

extern "C" void kernel_launch(void* const* d_in, const int* in_sizes, int n_in,
                              void* d_out, int out_size)
{
    const float* node_input = (const float*)d_in[0];
    const float* node_attr  = (const float*)d_in[1];
    const int*   edge_src   = (const int*)  d_in[2];
    const int*   edge_dst   = (const int*)  d_in[3];
    const float* edge_attr  = (const float*)d_in[4];
    const float* ele        = (const float*)d_in[5];
    const float* sc_w0      = (const float*)d_in[6];
    const float* sc_w1      = (const float*)d_in[7];
    const float* lin1_w0    = (const float*)d_in[8];
    const float* lin1_w1    = (const float*)d_in[9];
    const float* fc_w0      = (const float*)d_in[10];
    const float* fc_w1      = (const float*)d_in[11];
    const float* lin2_w0    = (const float*)d_in[12];
    const float* lin2_w1    = (const float*)d_in[13];
    const float* lin2_w2    = (const float*)d_in[14];
    float* out = (float*)d_out;

    // k_gemm is the 4th launch — the observed ncu capture slot.
    k_zero<<<(NN + 255) / 256, 256>>>();
    k_hist<<<(NE + 255) / 256, 256>>>(edge_dst);
    k_scan<<<1, 512>>>();
    k_gemm<<<NE / GE, 320>>>(ele, fc_w0, fc_w1);
    k_tw<<<(23552 + 255) / 256, 256>>>(lin2_w0, lin2_w1, lin2_w2, lin1_w0, lin1_w1, sc_w0, sc_w1);
    k_node<<<NN, 160>>>(node_input, node_attr);
    k_fill<<<(NE + 255) / 256, 256>>>(edge_dst);
    k_gather<<<NN, 320>>>(edge_attr, edge_src, node_attr, out);
}

// round 11
// speedup vs baseline: 1.6946x; 1.3886x over previous
#include <cuda_runtime.h>

#define NN 10000
#define NE 160000

#define SILU_C_F   1.6765867f
#define INV_S8     0.35355339059327373f
#define INV_S32    0.17677669529663687f
#define INV_S96    0.10206207261596575f
#define INV_S128   0.08838834764831845f
#define INV_S3     0.57735026918962576f
#define S3_DIV_S5  0.77459666924148338f   // sqrt(3/5)
#define IS2        0.70710678118654752f   // 1/sqrt(2)
#define IS6        0.40824829046386302f   // 1/sqrt(6)
#define C_S        0.38268343236508977f   // sin(pi/8)
#define C_X        0.92387953251128676f   // cos(pi/8)

// scratch
__device__ float g_y[NN * 160];
__device__ float g_s[NN * 160];     // self-connection, C_S pre-folded
__device__ float g_w[NE * 320];     // per-edge TP weights (GEMM output)
__device__ float g_agg[NN * 960];   // gathered accumulators [m(96)|m1T(384)|m2T(480)]
// sort scratch
__device__ int g_count[NN];
__device__ int g_fill[NN];
__device__ int g_offset[NN + 1];
__device__ int g_perm[NE];

__device__ __forceinline__ unsigned long long pack2(float x) {
    unsigned long long r; asm("mov.b64 %0, {%1, %1};" : "=l"(r) : "f"(x)); return r;
}
__device__ __forceinline__ void fma2(unsigned long long& d, unsigned long long a, unsigned long long b) {
    asm("fma.rn.f32x2 %0, %1, %2, %0;" : "+l"(d) : "l"(a), "l"(b));
}
__device__ __forceinline__ float2 unpack2(unsigned long long v) {
    float2 f; asm("mov.b64 {%0, %1}, %2;" : "=f"(f.x), "=f"(f.y) : "l"(v)); return f;
}

// ---------------- zero counters ----------------
__global__ void k_zero() {
    int i = blockIdx.x * blockDim.x + threadIdx.x;
    if (i < NN) { g_count[i] = 0; g_fill[i] = 0; }
}

// ---------------- histogram / scan / permutation ----------------
__global__ void k_hist(const int* __restrict__ edge_dst) {
    int i = blockIdx.x * blockDim.x + threadIdx.x;
    if (i < NE) atomicAdd(&g_count[edge_dst[i]], 1);
}
__global__ __launch_bounds__(512) void k_scan() {
    __shared__ int part[512];
    int t = threadIdx.x;
    int base = t * 20;
    int s = 0;
    #pragma unroll
    for (int i = 0; i < 20; i++) { int idx = base + i; if (idx < NN) s += g_count[idx]; }
    part[t] = s;
    __syncthreads();
    for (int d = 1; d < 512; d <<= 1) {
        int v = (t >= d) ? part[t - d] : 0;
        __syncthreads();
        part[t] += v;
        __syncthreads();
    }
    int run = (t > 0) ? part[t - 1] : 0;
    for (int i = 0; i < 20; i++) {
        int idx = base + i;
        if (idx < NN) { g_offset[idx] = run; run += g_count[idx]; }
    }
    if (t == 511) g_offset[NN] = run;
}
__global__ void k_fill(const int* __restrict__ edge_dst) {
    int e = blockIdx.x * blockDim.x + threadIdx.x;
    if (e < NE) {
        int d = edge_dst[e];
        int p = atomicAdd(&g_fill[d], 1);
        g_perm[g_offset[d] + p] = e;
    }
}

// ---------------- node pre-linear: 16-node tile, col-owner, coalesced weights ----------------
__global__ __launch_bounds__(160) void k_node(
    const float* __restrict__ node_input, const float* __restrict__ node_attr,
    const float* __restrict__ lin1_w0, const float* __restrict__ sc_w0,
    const float* __restrict__ lin1_w1, const float* __restrict__ sc_w1)
{
    __shared__ float xs[16][160];
    __shared__ float natt[16];
    int n0 = blockIdx.x * 16, t = threadIdx.x;
    for (int idx = t; idx < 16 * 160; idx += 160) {
        int nn = idx / 160, col = idx - nn * 160;
        xs[nn][col] = node_input[(n0 + nn) * 160 + col];
    }
    if (t < 16) natt[t] = node_attr[n0 + t];
    __syncthreads();

    float accy[16], accs[16];
    #pragma unroll
    for (int nn = 0; nn < 16; nn++) { accy[nn] = 0.f; accs[nn] = 0.f; }

    if (t < 64) {
        #pragma unroll 1
        for (int uc = 0; uc < 64; uc += 16) {
            float wl[16], ws[16];
            #pragma unroll
            for (int q = 0; q < 16; q++) {
                wl[q] = __ldg(&lin1_w0[(uc + q) * 64 + t]);
                ws[q] = __ldg(&sc_w0[(uc + q) * 64 + t]);
            }
            #pragma unroll
            for (int nn = 0; nn < 16; nn++) {
                #pragma unroll
                for (int q = 0; q < 16; q += 4) {
                    float4 xv = *reinterpret_cast<const float4*>(&xs[nn][uc + q]);
                    accy[nn] = fmaf(xv.x, wl[q], fmaf(xv.y, wl[q+1], fmaf(xv.z, wl[q+2], fmaf(xv.w, wl[q+3], accy[nn]))));
                    accs[nn] = fmaf(xv.x, ws[q], fmaf(xv.y, ws[q+1], fmaf(xv.z, ws[q+2], fmaf(xv.w, ws[q+3], accs[nn]))));
                }
            }
        }
        #pragma unroll
        for (int nn = 0; nn < 16; nn++) {
            float a = natt[nn];
            g_y[(n0 + nn) * 160 + t] = accy[nn] * a * 0.125f;
            g_s[(n0 + nn) * 160 + t] = accs[nn] * a * (0.125f * C_S);
        }
    } else {
        int j = t - 64, v = j / 3, i = j - 3 * v;
        #pragma unroll 1
        for (int uc = 0; uc < 32; uc += 16) {
            float wl[16], ws[16];
            #pragma unroll
            for (int q = 0; q < 16; q++) {
                wl[q] = __ldg(&lin1_w1[(uc + q) * 32 + v]);
                ws[q] = __ldg(&sc_w1[(uc + q) * 32 + v]);
            }
            #pragma unroll
            for (int nn = 0; nn < 16; nn++) {
                #pragma unroll
                for (int q = 0; q < 16; q++) {
                    float xv = xs[nn][64 + (uc + q) * 3 + i];
                    accy[nn] = fmaf(xv, wl[q], accy[nn]);
                    accs[nn] = fmaf(xv, ws[q], accs[nn]);
                }
            }
        }
        #pragma unroll
        for (int nn = 0; nn < 16; nn++) {
            float a = natt[nn];
            g_y[(n0 + nn) * 160 + t] = accy[nn] * a * INV_S32;
            g_s[(n0 + nn) * 160 + t] = accs[nn] * a * (INV_S32 * C_S);
        }
    }
}

// ---------------- GEMM: W[e][c] = h(e) . fc_w1[:,c]; 4 cols x 8 edges per thread ----------------
#define GE 16
__global__ __launch_bounds__(160) void k_gemm(
    const float* __restrict__ ele, const float* __restrict__ fc_w0,
    const float* __restrict__ fc_w1)
{
    __shared__ float s_el[GE * 8];
    __shared__ float s_w0[512];
    __shared__ float sHT[64 * GE];   // sHT[k*16 + e]
    int t = threadIdx.x;
    int eb = blockIdx.x * GE;

    if (t < GE * 8) s_el[t] = ele[eb * 8 + t];
    for (int i = t; i < 512; i += 160) s_w0[i] = fc_w0[i];
    __syncthreads();

    // h: t<128 -> c = t>>1, edges (t&1)*8 .. +7
    if (t < 128) {
        int c = t >> 1, e0h = (t & 1) * 8;
        #pragma unroll
        for (int j = 0; j < 8; j++) {
            int e = e0h + j;
            float z = 0.f;
            #pragma unroll
            for (int k = 0; k < 8; k++) z = fmaf(s_el[e * 8 + k], s_w0[k * 64 + c], z);
            z *= INV_S8;
            float sg = __fdividef(1.f, 1.f + __expf(-z));
            sHT[c * GE + e] = z * sg * (SILU_C_F * 0.03125f);
        }
    }
    __syncthreads();

    int cq = t % 80;          // col quad: cols c0..c0+3
    int eq = t / 80;          // edge half: edges eq*8..+7
    int c0 = cq * 4;
    int e0 = eq * 8;

    unsigned long long acc[4][4];   // [col j][edge pair p]
    #pragma unroll
    for (int j = 0; j < 4; j++)
        #pragma unroll
        for (int p = 0; p < 4; p++) acc[j][p] = 0ULL;

    #pragma unroll 4
    for (int k = 0; k < 64; k++) {
        float4 wv = __ldg(reinterpret_cast<const float4*>(&fc_w1[k * 320 + c0]));
        unsigned long long w0 = pack2(wv.x), w1 = pack2(wv.y), w2 = pack2(wv.z), w3 = pack2(wv.w);
        const ulonglong2* hp = reinterpret_cast<const ulonglong2*>(&sHT[k * GE + e0]);
        ulonglong2 ha = hp[0];   // edges e0..e0+3
        ulonglong2 hb = hp[1];   // edges e0+4..e0+7
        fma2(acc[0][0], ha.x, w0); fma2(acc[0][1], ha.y, w0); fma2(acc[0][2], hb.x, w0); fma2(acc[0][3], hb.y, w0);
        fma2(acc[1][0], ha.x, w1); fma2(acc[1][1], ha.y, w1); fma2(acc[1][2], hb.x, w1); fma2(acc[1][3], hb.y, w1);
        fma2(acc[2][0], ha.x, w2); fma2(acc[2][1], ha.y, w2); fma2(acc[2][2], hb.x, w2); fma2(acc[2][3], hb.y, w2);
        fma2(acc[3][0], ha.x, w3); fma2(acc[3][1], ha.y, w3); fma2(acc[3][2], hb.x, w3); fma2(acc[3][3], hb.y, w3);
    }

    // store: per edge, 4 consecutive cols -> STG.128, coalesced across cq
    #pragma unroll
    for (int p = 0; p < 4; p++) {
        float2 v0 = unpack2(acc[0][p]), v1 = unpack2(acc[1][p]);
        float2 v2 = unpack2(acc[2][p]), v3 = unpack2(acc[3][p]);
        float4 lo = make_float4(v0.x, v1.x, v2.x, v3.x);
        float4 hi = make_float4(v0.y, v1.y, v2.y, v3.y);
        *reinterpret_cast<float4*>(&g_w[(eb + e0 + 2 * p) * 320 + c0]) = lo;
        *reinterpret_cast<float4*>(&g_w[(eb + e0 + 2 * p + 1) * 320 + c0]) = hi;
    }
}

// ---------------- gather: per dst node; writes agg (no lin2 tail) ----------------
// thread t ownership (verified):
//   [0,64): k0  | [64,128): k2  | [128,192): k5 | [192,224): k3
//   [224,256): k1 | [256,288): k6 | [288,320): k4
__global__ __launch_bounds__(320) void k_gather(
    const float* __restrict__ edge_attr, const int* __restrict__ edge_src)
{
    __shared__ float mall[960];      // [m(96) | m1T(384) | m2T(480)]
    __shared__ int sed[64];
    __shared__ int ssrc[64];
    float* m   = mall;
    float* m1T = mall + 96;
    float* m2T = mall + 480;

    int n = blockIdx.x, t = threadIdx.x;
    int off = g_offset[n];
    int degAll = g_offset[n + 1] - off;
    float acc0 = 0.f, acc1 = 0.f, acc2 = 0.f, acc3 = 0.f, acc4 = 0.f;

    int eabase, ean;
    if      (t < 64)  { eabase = 0; ean = 1; }
    else if (t < 128) { eabase = 1; ean = 3; }
    else if (t < 192) { eabase = 4; ean = 5; }
    else if (t < 224) { eabase = 0; ean = 1; }
    else if (t < 288) { eabase = 1; ean = 3; }
    else              { eabase = 4; ean = 5; }

    for (int tile = 0; tile < degAll; tile += 64) {
        int deg = degAll - tile; if (deg > 64) deg = 64;
        __syncthreads();
        if (t < deg) {
            int e = __ldg(&g_perm[off + tile + t]);
            sed[t] = e;
            ssrc[t] = __ldg(&edge_src[e]);
        }
        __syncthreads();

        int ed = sed[0], src = ssrc[0];
        float wv = __ldg(&g_w[ed * 320 + t]);
        float y0, y1 = 0.f, y2 = 0.f;
        if (t < 192) y0 = __ldg(&g_y[src * 160 + (t & 63)]);
        else { const float* yp = &g_y[src * 160 + 64 + 3 * ((t - 192) & 31)];
               y0 = __ldg(yp); y1 = __ldg(yp + 1); y2 = __ldg(yp + 2); }
        float er[5];
        #pragma unroll
        for (int j = 0; j < 5; j++) er[j] = (j < ean) ? __ldg(&edge_attr[ed * 9 + eabase + j]) : 0.f;

        for (int i = 0; i < deg; i++) {
            float wv_n = 0.f, y0_n = 0.f, y1_n = 0.f, y2_n = 0.f;
            float er_n[5] = {0.f, 0.f, 0.f, 0.f, 0.f};
            if (i + 1 < deg) {
                int edn = sed[i + 1], srcn = ssrc[i + 1];
                wv_n = __ldg(&g_w[edn * 320 + t]);
                if (t < 192) y0_n = __ldg(&g_y[srcn * 160 + (t & 63)]);
                else { const float* yp = &g_y[srcn * 160 + 64 + 3 * ((t - 192) & 31)];
                       y0_n = __ldg(yp); y1_n = __ldg(yp + 1); y2_n = __ldg(yp + 2); }
                #pragma unroll
                for (int j = 0; j < 5; j++) if (j < ean) er_n[j] = __ldg(&edge_attr[edn * 9 + eabase + j]);
            }

            if (t < 64) {
                acc0 = fmaf(y0 * er[0], wv, acc0);
            } else if (t < 128) {
                float b = y0 * wv;
                acc0 = fmaf(b, er[0], acc0); acc1 = fmaf(b, er[1], acc1); acc2 = fmaf(b, er[2], acc2);
            } else if (t < 192) {
                float b = y0 * wv;
                acc0 = fmaf(b, er[0], acc0); acc1 = fmaf(b, er[1], acc1); acc2 = fmaf(b, er[2], acc2);
                acc3 = fmaf(b, er[3], acc3); acc4 = fmaf(b, er[4], acc4);
            } else if (t < 224) {
                float b = er[0] * wv;
                acc0 = fmaf(b, y0, acc0); acc1 = fmaf(b, y1, acc1); acc2 = fmaf(b, y2, acc2);
            } else if (t < 256) {
                acc0 = fmaf(INV_S3 * wv, fmaf(y0, er[0], fmaf(y1, er[1], y2 * er[2])), acc0);
            } else if (t < 288) {
                float s = -wv;
                acc0 = fmaf(s, (y2 * er[0] + y0 * er[2]) * IS2, acc0);
                acc1 = fmaf(s, (y0 * er[1] + y1 * er[0]) * IS2, acc1);
                acc2 = fmaf(s, (-y0 * er[0] + 2.f * y1 * er[1] - y2 * er[2]) * IS6, acc2);
                acc3 = fmaf(s, (y1 * er[2] + y2 * er[1]) * IS2, acc3);
                acc4 = fmaf(s, (-y0 * er[0] + y2 * er[2]) * IS2, acc4);
            } else {
                float p0 = er[0], p1 = er[1], p2 = er[2], p3 = er[3], p4 = er[4];
                float Myy = -p2 * IS6 - p4 * IS2;
                float Mzz =  2.f * p2 * IS6;
                float Mxx = -p2 * IS6 + p4 * IS2;
                float Myz =  p1 * IS2;
                float Myx =  p0 * IS2;
                float Mzx =  p3 * IS2;
                float s = S3_DIV_S5 * wv;
                acc0 = fmaf(s, fmaf(Myy, y0, fmaf(Myz, y1, Myx * y2)), acc0);
                acc1 = fmaf(s, fmaf(Myz, y0, fmaf(Mzz, y1, Mzx * y2)), acc1);
                acc2 = fmaf(s, fmaf(Myx, y0, fmaf(Mzx, y1, Mxx * y2)), acc2);
            }
            wv = wv_n; y0 = y0_n; y1 = y1_n; y2 = y2_n;
            #pragma unroll
            for (int j = 0; j < 5; j++) er[j] = er_n[j];
        }
    }

    // stage accumulators into lin2-friendly smem layouts
    if (t < 64) {
        m[t] = acc0;
    } else if (t < 128) {
        int u = t - 64;
        m1T[u] = acc0; m1T[128 + u] = acc1; m1T[256 + u] = acc2;
    } else if (t < 192) {
        int u = t - 128;
        m2T[u] = acc0; m2T[96 + u] = acc1; m2T[192 + u] = acc2;
        m2T[288 + u] = acc3; m2T[384 + u] = acc4;
    } else if (t < 224) {
        int v = t - 192 + 64;
        m1T[v] = acc0; m1T[128 + v] = acc1; m1T[256 + v] = acc2;
    } else if (t < 256) {
        m[64 + (t - 224)] = acc0;
    } else if (t < 288) {
        int v = t - 256 + 64;
        m2T[v] = acc0; m2T[96 + v] = acc1; m2T[192 + v] = acc2;
        m2T[288 + v] = acc3; m2T[384 + v] = acc4;
    } else {
        int v = t - 288 + 96;
        m1T[v] = acc0; m1T[128 + v] = acc1; m1T[256 + v] = acc2;
    }
    __syncthreads();

    for (int idx = t; idx < 960; idx += 320)
        g_agg[n * 960 + idx] = mall[idx];
}

// ---------------- output: lin2 + combine; 16-node tile, col-owner, coalesced weights ----------------
__global__ __launch_bounds__(320) void k_out(
    const float* __restrict__ node_attr,
    const float* __restrict__ lin2_w0, const float* __restrict__ lin2_w1,
    const float* __restrict__ lin2_w2, float* __restrict__ out)
{
    extern __shared__ float sag[];   // [16][960]
    __shared__ float natt[16];
    int n0 = blockIdx.x * 16, t = threadIdx.x;
    for (int idx = t; idx < 16 * 960; idx += 320)
        sag[idx] = g_agg[n0 * 960 + idx];
    if (t < 16) natt[t] = node_attr[n0 + t];
    __syncthreads();

    float acc[16];
    #pragma unroll
    for (int nn = 0; nn < 16; nn++) acc[nn] = 0.f;

    if (t < 64) {
        #pragma unroll 1
        for (int pc = 0; pc < 96; pc += 16) {
            float w[16];
            #pragma unroll
            for (int q = 0; q < 16; q++) w[q] = __ldg(&lin2_w0[(pc + q) * 64 + t]);
            #pragma unroll
            for (int nn = 0; nn < 16; nn++) {
                const float* mp = &sag[nn * 960 + pc];
                #pragma unroll
                for (int q = 0; q < 16; q += 4) {
                    float4 mv = *reinterpret_cast<const float4*>(mp + q);
                    acc[nn] = fmaf(mv.x, w[q], fmaf(mv.y, w[q+1], fmaf(mv.z, w[q+2], fmaf(mv.w, w[q+3], acc[nn]))));
                }
            }
        }
        #pragma unroll
        for (int nn = 0; nn < 16; nn++) {
            int n = n0 + nn;
            out[n * 320 + t] = __ldg(&g_s[n * 160 + t]) + acc[nn] * natt[nn] * (C_X * INV_S96);
        }
    } else if (t < 160) {
        int j = t - 64, v = j / 3, i = j - 3 * v;
        #pragma unroll 1
        for (int pc = 0; pc < 128; pc += 16) {
            float w[16];
            #pragma unroll
            for (int q = 0; q < 16; q++) w[q] = __ldg(&lin2_w1[(pc + q) * 32 + v]);
            #pragma unroll
            for (int nn = 0; nn < 16; nn++) {
                const float* mp = &sag[nn * 960 + 96 + i * 128 + pc];
                #pragma unroll
                for (int q = 0; q < 16; q += 4) {
                    float4 mv = *reinterpret_cast<const float4*>(mp + q);
                    acc[nn] = fmaf(mv.x, w[q], fmaf(mv.y, w[q+1], fmaf(mv.z, w[q+2], fmaf(mv.w, w[q+3], acc[nn]))));
                }
            }
        }
        #pragma unroll
        for (int nn = 0; nn < 16; nn++) {
            int n = n0 + nn;
            out[n * 320 + t] = __ldg(&g_s[n * 160 + t]) + acc[nn] * natt[nn] * (C_X * INV_S128);
        }
    } else {
        int j = t - 160, v = j / 5, i = j - 5 * v;
        #pragma unroll 1
        for (int pc = 0; pc < 96; pc += 16) {
            float w[16];
            #pragma unroll
            for (int q = 0; q < 16; q++) w[q] = __ldg(&lin2_w2[(pc + q) * 32 + v]);
            #pragma unroll
            for (int nn = 0; nn < 16; nn++) {
                const float* mp = &sag[nn * 960 + 480 + i * 96 + pc];
                #pragma unroll
                for (int q = 0; q < 16; q += 4) {
                    float4 mv = *reinterpret_cast<const float4*>(mp + q);
                    acc[nn] = fmaf(mv.x, w[q], fmaf(mv.y, w[q+1], fmaf(mv.z, w[q+2], fmaf(mv.w, w[q+3], acc[nn]))));
                }
            }
        }
        #pragma unroll
        for (int nn = 0; nn < 16; nn++) {
            int n = n0 + nn;
            out[n * 320 + t] = acc[nn] * natt[nn] * INV_S96;
        }
    }
}

extern "C" void kernel_launch(void* const* d_in, const int* in_sizes, int n_in,
                              void* d_out, int out_size)
{
    const float* node_input = (const float*)d_in[0];
    const float* node_attr  = (const float*)d_in[1];
    const int*   edge_src   = (const int*)  d_in[2];
    const int*   edge_dst   = (const int*)  d_in[3];
    const float* edge_attr  = (const float*)d_in[4];
    const float* ele        = (const float*)d_in[5];
    const float* sc_w0      = (const float*)d_in[6];
    const float* sc_w1      = (const float*)d_in[7];
    const float* lin1_w0    = (const float*)d_in[8];
    const float* lin1_w1    = (const float*)d_in[9];
    const float* fc_w0      = (const float*)d_in[10];
    const float* fc_w1      = (const float*)d_in[11];
    const float* lin2_w0    = (const float*)d_in[12];
    const float* lin2_w1    = (const float*)d_in[13];
    const float* lin2_w2    = (const float*)d_in[14];
    float* out = (float*)d_out;

    const int smem_out = 16 * 960 * 4;   // 60 KB
    cudaFuncSetAttribute(k_out, cudaFuncAttributeMaxDynamicSharedMemorySize, smem_out);

    // k_gemm in the 4th launch slot (observed ncu capture slot)
    k_zero<<<(NN + 255) / 256, 256>>>();
    k_hist<<<(NE + 255) / 256, 256>>>(edge_dst);
    k_scan<<<1, 512>>>();
    k_gemm<<<NE / GE, 160>>>(ele, fc_w0, fc_w1);
    k_fill<<<(NE + 255) / 256, 256>>>(edge_dst);
    k_node<<<NN / 16, 160>>>(node_input, node_attr, lin1_w0, sc_w0, lin1_w1, sc_w1);
    k_gather<<<NN, 320>>>(edge_attr, edge_src);
    k_out<<<NN / 16, 320, smem_out>>>(node_attr, lin2_w0, lin2_w1, lin2_w2, out);
}

// round 12
// speedup vs baseline: 1.8896x; 1.1151x over previous
#include <cuda_runtime.h>

#define NN 10000
#define NE 160000

#define SILU_C_F   1.6765867f
#define INV_S8     0.35355339059327373f
#define INV_S32    0.17677669529663687f
#define INV_S96    0.10206207261596575f
#define INV_S128   0.08838834764831845f
#define INV_S3     0.57735026918962576f
#define S3_DIV_S5  0.77459666924148338f   // sqrt(3/5)
#define IS2        0.70710678118654752f   // 1/sqrt(2)
#define IS6        0.40824829046386302f   // 1/sqrt(6)
#define C_S        0.38268343236508977f   // sin(pi/8)
#define C_X        0.92387953251128676f   // cos(pi/8)

// scratch
__device__ float g_y[NN * 160];
__device__ float g_s[NN * 160];     // self-connection, C_S pre-folded
__device__ float g_w[NE * 320];     // per-edge TP weights (GEMM output)
__device__ float g_agg[NN * 960];   // gathered accumulators [m(96)|m1T(384)|m2T(480)]
// sort scratch
__device__ int g_count[NN];
__device__ int g_fill[NN];
__device__ int g_offset[NN + 1];
__device__ int g_perm[NE];

__device__ __forceinline__ unsigned long long pack2(float x) {
    unsigned long long r; asm("mov.b64 %0, {%1, %1};" : "=l"(r) : "f"(x)); return r;
}
__device__ __forceinline__ void fma2(unsigned long long& d, unsigned long long a, unsigned long long b) {
    asm("fma.rn.f32x2 %0, %1, %2, %0;" : "+l"(d) : "l"(a), "l"(b));
}
__device__ __forceinline__ float2 unpack2(unsigned long long v) {
    float2 f; asm("mov.b64 {%0, %1}, %2;" : "=f"(f.x), "=f"(f.y) : "l"(v)); return f;
}

// ---------------- zero counters ----------------
__global__ void k_zero() {
    int i = blockIdx.x * blockDim.x + threadIdx.x;
    if (i < NN) { g_count[i] = 0; g_fill[i] = 0; }
}

// ---------------- histogram / scan / permutation ----------------
__global__ void k_hist(const int* __restrict__ edge_dst) {
    int i = blockIdx.x * blockDim.x + threadIdx.x;
    if (i < NE) atomicAdd(&g_count[edge_dst[i]], 1);
}
__global__ __launch_bounds__(512) void k_scan() {
    __shared__ int part[512];
    int t = threadIdx.x;
    int base = t * 20;
    int s = 0;
    #pragma unroll
    for (int i = 0; i < 20; i++) { int idx = base + i; if (idx < NN) s += g_count[idx]; }
    part[t] = s;
    __syncthreads();
    for (int d = 1; d < 512; d <<= 1) {
        int v = (t >= d) ? part[t - d] : 0;
        __syncthreads();
        part[t] += v;
        __syncthreads();
    }
    int run = (t > 0) ? part[t - 1] : 0;
    for (int i = 0; i < 20; i++) {
        int idx = base + i;
        if (idx < NN) { g_offset[idx] = run; run += g_count[idx]; }
    }
    if (t == 511) g_offset[NN] = run;
}
__global__ void k_fill(const int* __restrict__ edge_dst) {
    int e = blockIdx.x * blockDim.x + threadIdx.x;
    if (e < NE) {
        int d = edge_dst[e];
        int p = atomicAdd(&g_fill[d], 1);
        g_perm[g_offset[d] + p] = e;
    }
}

// ---------------- node pre-linear: 16-node tile, col-owner, coalesced weights ----------------
__global__ __launch_bounds__(160) void k_node(
    const float* __restrict__ node_input, const float* __restrict__ node_attr,
    const float* __restrict__ lin1_w0, const float* __restrict__ sc_w0,
    const float* __restrict__ lin1_w1, const float* __restrict__ sc_w1)
{
    __shared__ float xs[16][160];
    __shared__ float natt[16];
    int n0 = blockIdx.x * 16, t = threadIdx.x;
    for (int idx = t; idx < 16 * 160; idx += 160) {
        int nn = idx / 160, col = idx - nn * 160;
        xs[nn][col] = node_input[(n0 + nn) * 160 + col];
    }
    if (t < 16) natt[t] = node_attr[n0 + t];
    __syncthreads();

    float accy[16], accs[16];
    #pragma unroll
    for (int nn = 0; nn < 16; nn++) { accy[nn] = 0.f; accs[nn] = 0.f; }

    if (t < 64) {
        #pragma unroll 1
        for (int uc = 0; uc < 64; uc += 16) {
            float wl[16], ws[16];
            #pragma unroll
            for (int q = 0; q < 16; q++) {
                wl[q] = __ldg(&lin1_w0[(uc + q) * 64 + t]);
                ws[q] = __ldg(&sc_w0[(uc + q) * 64 + t]);
            }
            #pragma unroll
            for (int nn = 0; nn < 16; nn++) {
                #pragma unroll
                for (int q = 0; q < 16; q += 4) {
                    float4 xv = *reinterpret_cast<const float4*>(&xs[nn][uc + q]);
                    accy[nn] = fmaf(xv.x, wl[q], fmaf(xv.y, wl[q+1], fmaf(xv.z, wl[q+2], fmaf(xv.w, wl[q+3], accy[nn]))));
                    accs[nn] = fmaf(xv.x, ws[q], fmaf(xv.y, ws[q+1], fmaf(xv.z, ws[q+2], fmaf(xv.w, ws[q+3], accs[nn]))));
                }
            }
        }
        #pragma unroll
        for (int nn = 0; nn < 16; nn++) {
            float a = natt[nn];
            g_y[(n0 + nn) * 160 + t] = accy[nn] * a * 0.125f;
            g_s[(n0 + nn) * 160 + t] = accs[nn] * a * (0.125f * C_S);
        }
    } else {
        int j = t - 64, v = j / 3, i = j - 3 * v;
        #pragma unroll 1
        for (int uc = 0; uc < 32; uc += 16) {
            float wl[16], ws[16];
            #pragma unroll
            for (int q = 0; q < 16; q++) {
                wl[q] = __ldg(&lin1_w1[(uc + q) * 32 + v]);
                ws[q] = __ldg(&sc_w1[(uc + q) * 32 + v]);
            }
            #pragma unroll
            for (int nn = 0; nn < 16; nn++) {
                #pragma unroll
                for (int q = 0; q < 16; q++) {
                    float xv = xs[nn][64 + (uc + q) * 3 + i];
                    accy[nn] = fmaf(xv, wl[q], accy[nn]);
                    accs[nn] = fmaf(xv, ws[q], accs[nn]);
                }
            }
        }
        #pragma unroll
        for (int nn = 0; nn < 16; nn++) {
            float a = natt[nn];
            g_y[(n0 + nn) * 160 + t] = accy[nn] * a * INV_S32;
            g_s[(n0 + nn) * 160 + t] = accs[nn] * a * (INV_S32 * C_S);
        }
    }
}

// ---------------- GEMM: W[e][c] = h(e) . fc_w1[:,c]; 4 cols x 8 edges per thread ----------------
#define GE 16
__global__ __launch_bounds__(160) void k_gemm(
    const float* __restrict__ ele, const float* __restrict__ fc_w0,
    const float* __restrict__ fc_w1)
{
    __shared__ float s_el[GE * 8];
    __shared__ float s_w0[512];
    __shared__ float sHT[64 * GE];   // sHT[k*16 + e]
    int t = threadIdx.x;
    int eb = blockIdx.x * GE;

    if (t < GE * 8) s_el[t] = ele[eb * 8 + t];
    for (int i = t; i < 512; i += 160) s_w0[i] = fc_w0[i];
    __syncthreads();

    if (t < 128) {
        int c = t >> 1, e0h = (t & 1) * 8;
        #pragma unroll
        for (int j = 0; j < 8; j++) {
            int e = e0h + j;
            float z = 0.f;
            #pragma unroll
            for (int k = 0; k < 8; k++) z = fmaf(s_el[e * 8 + k], s_w0[k * 64 + c], z);
            z *= INV_S8;
            float sg = __fdividef(1.f, 1.f + __expf(-z));
            sHT[c * GE + e] = z * sg * (SILU_C_F * 0.03125f);
        }
    }
    __syncthreads();

    int cq = t % 80;
    int eq = t / 80;
    int c0 = cq * 4;
    int e0 = eq * 8;

    unsigned long long acc[4][4];
    #pragma unroll
    for (int j = 0; j < 4; j++)
        #pragma unroll
        for (int p = 0; p < 4; p++) acc[j][p] = 0ULL;

    #pragma unroll 4
    for (int k = 0; k < 64; k++) {
        float4 wv = __ldg(reinterpret_cast<const float4*>(&fc_w1[k * 320 + c0]));
        unsigned long long w0 = pack2(wv.x), w1 = pack2(wv.y), w2 = pack2(wv.z), w3 = pack2(wv.w);
        const ulonglong2* hp = reinterpret_cast<const ulonglong2*>(&sHT[k * GE + e0]);
        ulonglong2 ha = hp[0];
        ulonglong2 hb = hp[1];
        fma2(acc[0][0], ha.x, w0); fma2(acc[0][1], ha.y, w0); fma2(acc[0][2], hb.x, w0); fma2(acc[0][3], hb.y, w0);
        fma2(acc[1][0], ha.x, w1); fma2(acc[1][1], ha.y, w1); fma2(acc[1][2], hb.x, w1); fma2(acc[1][3], hb.y, w1);
        fma2(acc[2][0], ha.x, w2); fma2(acc[2][1], ha.y, w2); fma2(acc[2][2], hb.x, w2); fma2(acc[2][3], hb.y, w2);
        fma2(acc[3][0], ha.x, w3); fma2(acc[3][1], ha.y, w3); fma2(acc[3][2], hb.x, w3); fma2(acc[3][3], hb.y, w3);
    }

    #pragma unroll
    for (int p = 0; p < 4; p++) {
        float2 v0 = unpack2(acc[0][p]), v1 = unpack2(acc[1][p]);
        float2 v2 = unpack2(acc[2][p]), v3 = unpack2(acc[3][p]);
        float4 lo = make_float4(v0.x, v1.x, v2.x, v3.x);
        float4 hi = make_float4(v0.y, v1.y, v2.y, v3.y);
        *reinterpret_cast<float4*>(&g_w[(eb + e0 + 2 * p) * 320 + c0]) = lo;
        *reinterpret_cast<float4*>(&g_w[(eb + e0 + 2 * p + 1) * 320 + c0]) = hi;
    }
}

// ---------------- gather v3: batched-MLP loads, edge_attr staged in smem ----------------
// thread t ownership (verified):
//   [0,64): k0  | [64,128): k2  | [128,192): k5 | [192,224): k3
//   [224,256): k1 | [256,288): k6 | [288,320): k4
__global__ __launch_bounds__(320) void k_gather(
    const float* __restrict__ edge_attr, const int* __restrict__ edge_src)
{
    __shared__ float mall[960];      // [m(96) | m1T(384) | m2T(480)]
    __shared__ int sed[64];
    __shared__ int ssrc[64];
    __shared__ float sea[64][10];    // staged edge_attr (9 used, pad to 10)
    float* m   = mall;
    float* m1T = mall + 96;
    float* m2T = mall + 480;

    int n = blockIdx.x, t = threadIdx.x;
    int off = g_offset[n];
    int degAll = g_offset[n + 1] - off;
    float acc0 = 0.f, acc1 = 0.f, acc2 = 0.f, acc3 = 0.f, acc4 = 0.f;

    int eabase;
    if      (t < 64)  eabase = 0;
    else if (t < 128) eabase = 1;
    else if (t < 192) eabase = 4;
    else if (t < 224) eabase = 0;
    else if (t < 288) eabase = 1;
    else              eabase = 4;

    for (int tile = 0; tile < degAll; tile += 64) {
        int deg = degAll - tile; if (deg > 64) deg = 64;
        __syncthreads();
        if (t < deg) {
            int e = __ldg(&g_perm[off + tile + t]);
            sed[t] = e;
            ssrc[t] = __ldg(&edge_src[e]);
        }
        __syncthreads();
        // stage edge_attr for this tile (high-MLP cooperative load)
        for (int idx = t; idx < deg * 9; idx += 320) {
            int e = idx / 9, j = idx - 9 * e;
            sea[e][j] = __ldg(&edge_attr[sed[e] * 9 + j]);
        }
        __syncthreads();

        for (int cb = 0; cb < deg; cb += 4) {
            // ---- batch loads (4 edges, independent -> MLP) ----
            float wv[4], ya[4], yb[4], yc[4];
            #pragma unroll
            for (int j = 0; j < 4; j++) {
                int ii = cb + j;
                bool act = ii < deg;
                int e = act ? sed[ii] : sed[0];
                int s = act ? ssrc[ii] : ssrc[0];
                wv[j] = __ldg(&g_w[e * 320 + t]);
                if (t < 192) {
                    ya[j] = __ldg(&g_y[s * 160 + (t & 63)]);
                    yb[j] = 0.f; yc[j] = 0.f;
                } else {
                    const float* yp = &g_y[s * 160 + 64 + 3 * ((t - 192) & 31)];
                    ya[j] = __ldg(yp); yb[j] = __ldg(yp + 1); yc[j] = __ldg(yp + 2);
                }
                if (!act) wv[j] = 0.f;   // wv=0 nullifies every path's contribution
            }
            // ---- consume batch ----
            #pragma unroll
            for (int j = 0; j < 4; j++) {
                int ii = cb + j; if (ii >= deg) ii = deg - 1;
                const float* er = &sea[ii][eabase];
                float w = wv[j], y0 = ya[j], y1 = yb[j], y2 = yc[j];
                if (t < 64) {
                    acc0 = fmaf(y0 * er[0], w, acc0);
                } else if (t < 128) {
                    float b = y0 * w;
                    acc0 = fmaf(b, er[0], acc0); acc1 = fmaf(b, er[1], acc1); acc2 = fmaf(b, er[2], acc2);
                } else if (t < 192) {
                    float b = y0 * w;
                    acc0 = fmaf(b, er[0], acc0); acc1 = fmaf(b, er[1], acc1); acc2 = fmaf(b, er[2], acc2);
                    acc3 = fmaf(b, er[3], acc3); acc4 = fmaf(b, er[4], acc4);
                } else if (t < 224) {
                    float b = er[0] * w;
                    acc0 = fmaf(b, y0, acc0); acc1 = fmaf(b, y1, acc1); acc2 = fmaf(b, y2, acc2);
                } else if (t < 256) {
                    acc0 = fmaf(INV_S3 * w, fmaf(y0, er[0], fmaf(y1, er[1], y2 * er[2])), acc0);
                } else if (t < 288) {
                    float s = -w;
                    acc0 = fmaf(s, (y2 * er[0] + y0 * er[2]) * IS2, acc0);
                    acc1 = fmaf(s, (y0 * er[1] + y1 * er[0]) * IS2, acc1);
                    acc2 = fmaf(s, (-y0 * er[0] + 2.f * y1 * er[1] - y2 * er[2]) * IS6, acc2);
                    acc3 = fmaf(s, (y1 * er[2] + y2 * er[1]) * IS2, acc3);
                    acc4 = fmaf(s, (-y0 * er[0] + y2 * er[2]) * IS2, acc4);
                } else {
                    float p0 = er[0], p1 = er[1], p2 = er[2], p3 = er[3], p4 = er[4];
                    float Myy = -p2 * IS6 - p4 * IS2;
                    float Mzz =  2.f * p2 * IS6;
                    float Mxx = -p2 * IS6 + p4 * IS2;
                    float Myz =  p1 * IS2;
                    float Myx =  p0 * IS2;
                    float Mzx =  p3 * IS2;
                    float s = S3_DIV_S5 * w;
                    acc0 = fmaf(s, fmaf(Myy, y0, fmaf(Myz, y1, Myx * y2)), acc0);
                    acc1 = fmaf(s, fmaf(Myz, y0, fmaf(Mzz, y1, Mzx * y2)), acc1);
                    acc2 = fmaf(s, fmaf(Myx, y0, fmaf(Mzx, y1, Mxx * y2)), acc2);
                }
            }
        }
    }

    // stage accumulators into lin2-friendly smem layouts
    if (t < 64) {
        m[t] = acc0;
    } else if (t < 128) {
        int u = t - 64;
        m1T[u] = acc0; m1T[128 + u] = acc1; m1T[256 + u] = acc2;
    } else if (t < 192) {
        int u = t - 128;
        m2T[u] = acc0; m2T[96 + u] = acc1; m2T[192 + u] = acc2;
        m2T[288 + u] = acc3; m2T[384 + u] = acc4;
    } else if (t < 224) {
        int v = t - 192 + 64;
        m1T[v] = acc0; m1T[128 + v] = acc1; m1T[256 + v] = acc2;
    } else if (t < 256) {
        m[64 + (t - 224)] = acc0;
    } else if (t < 288) {
        int v = t - 256 + 64;
        m2T[v] = acc0; m2T[96 + v] = acc1; m2T[192 + v] = acc2;
        m2T[288 + v] = acc3; m2T[384 + v] = acc4;
    } else {
        int v = t - 288 + 96;
        m1T[v] = acc0; m1T[128 + v] = acc1; m1T[256 + v] = acc2;
    }
    __syncthreads();

    for (int idx = t; idx < 960; idx += 320)
        g_agg[n * 960 + idx] = mall[idx];
}

// ---------------- output: lin2 + combine; 16-node tile, col-owner, coalesced weights ----------------
__global__ __launch_bounds__(320) void k_out(
    const float* __restrict__ node_attr,
    const float* __restrict__ lin2_w0, const float* __restrict__ lin2_w1,
    const float* __restrict__ lin2_w2, float* __restrict__ out)
{
    extern __shared__ float sag[];   // [16][960]
    __shared__ float natt[16];
    int n0 = blockIdx.x * 16, t = threadIdx.x;
    for (int idx = t; idx < 16 * 960; idx += 320)
        sag[idx] = g_agg[n0 * 960 + idx];
    if (t < 16) natt[t] = node_attr[n0 + t];
    __syncthreads();

    float acc[16];
    #pragma unroll
    for (int nn = 0; nn < 16; nn++) acc[nn] = 0.f;

    if (t < 64) {
        #pragma unroll 1
        for (int pc = 0; pc < 96; pc += 16) {
            float w[16];
            #pragma unroll
            for (int q = 0; q < 16; q++) w[q] = __ldg(&lin2_w0[(pc + q) * 64 + t]);
            #pragma unroll
            for (int nn = 0; nn < 16; nn++) {
                const float* mp = &sag[nn * 960 + pc];
                #pragma unroll
                for (int q = 0; q < 16; q += 4) {
                    float4 mv = *reinterpret_cast<const float4*>(mp + q);
                    acc[nn] = fmaf(mv.x, w[q], fmaf(mv.y, w[q+1], fmaf(mv.z, w[q+2], fmaf(mv.w, w[q+3], acc[nn]))));
                }
            }
        }
        #pragma unroll
        for (int nn = 0; nn < 16; nn++) {
            int n = n0 + nn;
            out[n * 320 + t] = __ldg(&g_s[n * 160 + t]) + acc[nn] * natt[nn] * (C_X * INV_S96);
        }
    } else if (t < 160) {
        int j = t - 64, v = j / 3, i = j - 3 * v;
        #pragma unroll 1
        for (int pc = 0; pc < 128; pc += 16) {
            float w[16];
            #pragma unroll
            for (int q = 0; q < 16; q++) w[q] = __ldg(&lin2_w1[(pc + q) * 32 + v]);
            #pragma unroll
            for (int nn = 0; nn < 16; nn++) {
                const float* mp = &sag[nn * 960 + 96 + i * 128 + pc];
                #pragma unroll
                for (int q = 0; q < 16; q += 4) {
                    float4 mv = *reinterpret_cast<const float4*>(mp + q);
                    acc[nn] = fmaf(mv.x, w[q], fmaf(mv.y, w[q+1], fmaf(mv.z, w[q+2], fmaf(mv.w, w[q+3], acc[nn]))));
                }
            }
        }
        #pragma unroll
        for (int nn = 0; nn < 16; nn++) {
            int n = n0 + nn;
            out[n * 320 + t] = __ldg(&g_s[n * 160 + t]) + acc[nn] * natt[nn] * (C_X * INV_S128);
        }
    } else {
        int j = t - 160, v = j / 5, i = j - 5 * v;
        #pragma unroll 1
        for (int pc = 0; pc < 96; pc += 16) {
            float w[16];
            #pragma unroll
            for (int q = 0; q < 16; q++) w[q] = __ldg(&lin2_w2[(pc + q) * 32 + v]);
            #pragma unroll
            for (int nn = 0; nn < 16; nn++) {
                const float* mp = &sag[nn * 960 + 480 + i * 96 + pc];
                #pragma unroll
                for (int q = 0; q < 16; q += 4) {
                    float4 mv = *reinterpret_cast<const float4*>(mp + q);
                    acc[nn] = fmaf(mv.x, w[q], fmaf(mv.y, w[q+1], fmaf(mv.z, w[q+2], fmaf(mv.w, w[q+3], acc[nn]))));
                }
            }
        }
        #pragma unroll
        for (int nn = 0; nn < 16; nn++) {
            int n = n0 + nn;
            out[n * 320 + t] = acc[nn] * natt[nn] * INV_S96;
        }
    }
}

extern "C" void kernel_launch(void* const* d_in, const int* in_sizes, int n_in,
                              void* d_out, int out_size)
{
    const float* node_input = (const float*)d_in[0];
    const float* node_attr  = (const float*)d_in[1];
    const int*   edge_src   = (const int*)  d_in[2];
    const int*   edge_dst   = (const int*)  d_in[3];
    const float* edge_attr  = (const float*)d_in[4];
    const float* ele        = (const float*)d_in[5];
    const float* sc_w0      = (const float*)d_in[6];
    const float* sc_w1      = (const float*)d_in[7];
    const float* lin1_w0    = (const float*)d_in[8];
    const float* lin1_w1    = (const float*)d_in[9];
    const float* fc_w0      = (const float*)d_in[10];
    const float* fc_w1      = (const float*)d_in[11];
    const float* lin2_w0    = (const float*)d_in[12];
    const float* lin2_w1    = (const float*)d_in[13];
    const float* lin2_w2    = (const float*)d_in[14];
    float* out = (float*)d_out;

    static cudaStream_t s2 = nullptr;
    static cudaEvent_t evA = nullptr, evB = nullptr;
    if (s2 == nullptr) {
        cudaStreamCreateWithFlags(&s2, cudaStreamNonBlocking);
        cudaEventCreateWithFlags(&evA, cudaEventDisableTiming);
        cudaEventCreateWithFlags(&evB, cudaEventDisableTiming);
    }

    const int smem_out = 16 * 960 * 4;   // 60 KB
    cudaFuncSetAttribute(k_out, cudaFuncAttributeMaxDynamicSharedMemorySize, smem_out);

    // fork: k_gemm (depends only on ele/fc_w*) runs concurrent with sort + node
    cudaEventRecord(evA, 0);
    cudaStreamWaitEvent(s2, evA, 0);
    k_gemm<<<NE / GE, 160, 0, s2>>>(ele, fc_w0, fc_w1);
    cudaEventRecord(evB, s2);

    k_zero<<<(NN + 255) / 256, 256>>>();
    k_hist<<<(NE + 255) / 256, 256>>>(edge_dst);
    k_scan<<<1, 512>>>();
    k_fill<<<(NE + 255) / 256, 256>>>(edge_dst);
    k_node<<<NN / 16, 160>>>(node_input, node_attr, lin1_w0, sc_w0, lin1_w1, sc_w1);

    // join: gather needs g_w (gemm), g_perm (fill), g_y (node)
    cudaStreamWaitEvent(0, evB, 0);
    k_gather<<<NN, 320>>>(edge_attr, edge_src);
    k_out<<<NN / 16, 320, smem_out>>>(node_attr, lin2_w0, lin2_w1, lin2_w2, out);
}